// round 2
// baseline (speedup 1.0000x reference)
#include <cuda_runtime.h>

// Problem constants (fixed by the dataset)
#define N_IMG 4096
#define N_POS 4096
#define N_NEG 4096
#define N_OTH 16384
#define DIM   128

// GEMM tiling
#define BM 128
#define BN 128
#define BK 32
#define PAD 4

// Scratch (device-global: no allocations allowed)
__device__ float g_x2[N_IMG];
__device__ float g_p2[N_POS];
__device__ float g_q2[N_NEG];
__device__ float g_m2[N_OTH];
__device__ float g_Spos[N_IMG];
__device__ float g_Sden[N_IMG];

__device__ __forceinline__ float ex2_approx(float x) {
    float r; asm("ex2.approx.f32 %0, %1;" : "=f"(r) : "f"(x)); return r;
}
__device__ __forceinline__ float sqrt_approx(float x) {
    float r; asm("sqrt.approx.f32 %0, %1;" : "=f"(r) : "f"(x)); return r;
}

// ---------------------------------------------------------------------------
// Kernel 1: squared norms for all rows of all 4 matrices + zero accumulators.
// One warp per row (128 floats = 1 float4 per lane).
// ---------------------------------------------------------------------------
__global__ void prep_kernel(const float* __restrict__ X, const float* __restrict__ P,
                            const float* __restrict__ Q, const float* __restrict__ M) {
    int gwarp = (blockIdx.x * blockDim.x + threadIdx.x) >> 5;
    int lane  = threadIdx.x & 31;
    const float* src; float* dst; int row;
    if (gwarp < N_IMG)                         { row = gwarp;                       src = X + (size_t)row * DIM; dst = g_x2; }
    else if (gwarp < N_IMG + N_POS)            { row = gwarp - N_IMG;               src = P + (size_t)row * DIM; dst = g_p2; }
    else if (gwarp < N_IMG + N_POS + N_NEG)    { row = gwarp - (N_IMG + N_POS);     src = Q + (size_t)row * DIM; dst = g_q2; }
    else                                       { row = gwarp - (N_IMG+N_POS+N_NEG); src = M + (size_t)row * DIM; dst = g_m2; }

    float4 v = ((const float4*)src)[lane];
    float s = v.x * v.x + v.y * v.y + v.z * v.z + v.w * v.w;
    #pragma unroll
    for (int o = 16; o > 0; o >>= 1) s += __shfl_xor_sync(0xFFFFFFFFu, s, o);
    if (lane == 0) {
        dst[row] = s;
        if (gwarp < N_IMG) { g_Spos[gwarp] = 0.0f; g_Sden[gwarp] = 0.0f; }
    }
}

// ---------------------------------------------------------------------------
// Kernel 2: fused tiled GEMM + distance + exp + per-row sum.
// grid = (32 row-tiles, 192 col-tiles). Col-tiles 0..31 -> positives (coef 4,
// accumulate to Spos), 32..63 -> negatives (coef 4, Sden), 64..191 -> other
// (coef 2, Sden). All segments are multiples of BN so every block lies in
// exactly one segment — no bounds checks anywhere.
// ---------------------------------------------------------------------------
__global__ __launch_bounds__(256, 2)
void softnn_main_kernel(const float* __restrict__ X, const float* __restrict__ Pm,
                        const float* __restrict__ Qm, const float* __restrict__ Mm) {
    __shared__ float As[BK][BM + PAD];
    __shared__ float Bs[BK][BN + PAD];

    const int rowTile = blockIdx.x;            // 0..31
    const int cb      = blockIdx.y;            // 0..191

    const float* Y; const float* y2g; float coef; float* target; int colBase;
    if (cb < 32)      { Y = Pm; y2g = g_p2; coef = 4.0f; target = g_Spos; colBase = cb * BN; }
    else if (cb < 64) { Y = Qm; y2g = g_q2; coef = 4.0f; target = g_Sden; colBase = (cb - 32) * BN; }
    else              { Y = Mm; y2g = g_m2; coef = 2.0f; target = g_Sden; colBase = (cb - 64) * BN; }

    const int tid = threadIdx.x;
    const int tx  = tid & 15;          // 0..15 -> 8 columns each
    const int ty  = tid >> 4;          // 0..15 -> 8 rows each
    const int rowBase = rowTile * BM;

    // loader mapping: 256 threads, each loads 4 float4 (one per pass)
    const int lr = tid >> 3;           // 0..31 : row within 32-row pass
    const int lk = (tid & 7) * 4;      // 0,4,...,28 : k offset

    float acc[8][8];
    #pragma unroll
    for (int i = 0; i < 8; i++)
        #pragma unroll
        for (int j = 0; j < 8; j++) acc[i][j] = 0.0f;

    #pragma unroll
    for (int kb = 0; kb < DIM; kb += BK) {
        #pragma unroll
        for (int p = 0; p < 4; ++p) {
            int r = lr + p * 32;
            float4 va = *(const float4*)&X[(size_t)(rowBase + r) * DIM + kb + lk];
            As[lk + 0][r] = va.x; As[lk + 1][r] = va.y;
            As[lk + 2][r] = va.z; As[lk + 3][r] = va.w;
            float4 vb = *(const float4*)&Y[(size_t)(colBase + r) * DIM + kb + lk];
            Bs[lk + 0][r] = vb.x; Bs[lk + 1][r] = vb.y;
            Bs[lk + 2][r] = vb.z; Bs[lk + 3][r] = vb.w;
        }
        __syncthreads();

        #pragma unroll
        for (int k = 0; k < BK; ++k) {
            float a[8], b[8];
            *(float4*)&a[0] = *(const float4*)&As[k][ty * 8];
            *(float4*)&a[4] = *(const float4*)&As[k][ty * 8 + 4];
            *(float4*)&b[0] = *(const float4*)&Bs[k][tx * 8];
            *(float4*)&b[4] = *(const float4*)&Bs[k][tx * 8 + 4];
            #pragma unroll
            for (int i = 0; i < 8; i++)
                #pragma unroll
                for (int j = 0; j < 8; j++)
                    acc[i][j] = fmaf(a[i], b[j], acc[i][j]);
        }
        __syncthreads();
    }

    // Epilogue: d = sqrt(max(x2 + y2 - 2*dot, 0)); accumulate exp(-coef*d)
    float x2v[8], y2v[8];
    #pragma unroll
    for (int i = 0; i < 8; i++) x2v[i] = g_x2[rowBase + ty * 8 + i];
    #pragma unroll
    for (int j = 0; j < 8; j++) y2v[j] = y2g[colBase + tx * 8 + j];

    const float nc = -coef * 1.4426950408889634f;   // -coef * log2(e)
    float rowsum[8];
    #pragma unroll
    for (int i = 0; i < 8; i++) rowsum[i] = 0.0f;

    #pragma unroll
    for (int i = 0; i < 8; i++) {
        #pragma unroll
        for (int j = 0; j < 8; j++) {
            float sq = fmaf(-2.0f, acc[i][j], x2v[i] + y2v[j]);
            sq = fmaxf(sq, 0.0f);
            float d = sqrt_approx(sq);
            rowsum[i] += ex2_approx(nc * d);
        }
    }

    // Reduce across the 16 threads (tx) that share each row; xor masks 1,2,4,8
    // stay inside each 16-lane half-warp (same ty).
    #pragma unroll
    for (int i = 0; i < 8; i++) {
        float s = rowsum[i];
        s += __shfl_xor_sync(0xFFFFFFFFu, s, 1);
        s += __shfl_xor_sync(0xFFFFFFFFu, s, 2);
        s += __shfl_xor_sync(0xFFFFFFFFu, s, 4);
        s += __shfl_xor_sync(0xFFFFFFFFu, s, 8);
        if (tx == 0) atomicAdd(&target[rowBase + ty * 8 + i], s);
    }
}

// ---------------------------------------------------------------------------
// Kernel 3: loss = sum_i ( log(Sden[i]) - log(Spos[i]) )
// ---------------------------------------------------------------------------
__global__ void final_kernel(float* __restrict__ out) {
    __shared__ double sm[256];
    int tid = threadIdx.x;
    double acc = 0.0;
    for (int i = tid; i < N_IMG; i += 256)
        acc += (double)(logf(g_Sden[i]) - logf(g_Spos[i]));
    sm[tid] = acc;
    __syncthreads();
    for (int o = 128; o > 0; o >>= 1) {
        if (tid < o) sm[tid] += sm[tid + o];
        __syncthreads();
    }
    if (tid == 0) out[0] = (float)sm[0];
}

// ---------------------------------------------------------------------------
extern "C" void kernel_launch(void* const* d_in, const int* in_sizes, int n_in,
                              void* d_out, int out_size) {
    const float* X = (const float*)d_in[0];   // image_views    [4096,128]
    const float* P = (const float*)d_in[1];   // positive_views [4096,128]
    const float* Q = (const float*)d_in[2];   // negative_views [4096,128]
    const float* M = (const float*)d_in[3];   // other_embeddings [16384,128]

    // 28672 rows total, one warp per row, 8 warps per block
    prep_kernel<<<(N_IMG + N_POS + N_NEG + N_OTH) / 8, 256>>>(X, P, Q, M);

    dim3 grid(N_IMG / BM, (N_POS + N_NEG + N_OTH) / BN);   // 32 x 192
    softnn_main_kernel<<<grid, 256>>>(X, P, Q, M);

    final_kernel<<<1, 256>>>((float*)d_out);
}

// round 3
// speedup vs baseline: 1.0006x; 1.0006x over previous
#include <cuda_runtime.h>

// Problem constants (fixed by the dataset)
#define N_IMG 4096
#define N_POS 4096
#define N_NEG 4096
#define N_OTH 16384
#define DIM   128

// GEMM tiling
#define BM 128
#define BN 128
#define BK 32
#define PAD 4

// Scratch (device-global: no allocations allowed)
__device__ float g_x2[N_IMG];
__device__ float g_p2[N_POS];
__device__ float g_q2[N_NEG];
__device__ float g_m2[N_OTH];
__device__ float g_Spos[N_IMG];
__device__ float g_Sden[N_IMG];

__device__ __forceinline__ float ex2_approx(float x) {
    float r; asm("ex2.approx.f32 %0, %1;" : "=f"(r) : "f"(x)); return r;
}
__device__ __forceinline__ float sqrt_approx(float x) {
    float r; asm("sqrt.approx.f32 %0, %1;" : "=f"(r) : "f"(x)); return r;
}

// ---------------------------------------------------------------------------
// Kernel 1: squared norms for all rows of all 4 matrices + zero accumulators.
// One warp per row (128 floats = 1 float4 per lane).
// ---------------------------------------------------------------------------
__global__ void prep_kernel(const float* __restrict__ X, const float* __restrict__ P,
                            const float* __restrict__ Q, const float* __restrict__ M) {
    int gwarp = (blockIdx.x * blockDim.x + threadIdx.x) >> 5;
    int lane  = threadIdx.x & 31;
    const float* src; float* dst; int row;
    if (gwarp < N_IMG)                         { row = gwarp;                       src = X + (size_t)row * DIM; dst = g_x2; }
    else if (gwarp < N_IMG + N_POS)            { row = gwarp - N_IMG;               src = P + (size_t)row * DIM; dst = g_p2; }
    else if (gwarp < N_IMG + N_POS + N_NEG)    { row = gwarp - (N_IMG + N_POS);     src = Q + (size_t)row * DIM; dst = g_q2; }
    else                                       { row = gwarp - (N_IMG+N_POS+N_NEG); src = M + (size_t)row * DIM; dst = g_m2; }

    float4 v = ((const float4*)src)[lane];
    float s = v.x * v.x + v.y * v.y + v.z * v.z + v.w * v.w;
    #pragma unroll
    for (int o = 16; o > 0; o >>= 1) s += __shfl_xor_sync(0xFFFFFFFFu, s, o);
    if (lane == 0) {
        dst[row] = s;
        if (gwarp < N_IMG) { g_Spos[gwarp] = 0.0f; g_Sden[gwarp] = 0.0f; }
    }
}

// ---------------------------------------------------------------------------
// Kernel 2: fused tiled GEMM + distance + exp + per-row sum.
// grid = (32 row-tiles, 192 col-tiles). Col-tiles 0..31 -> positives (coef 4,
// accumulate to Spos), 32..63 -> negatives (coef 4, Sden), 64..191 -> other
// (coef 2, Sden). All segments are multiples of BN so every block lies in
// exactly one segment — no bounds checks anywhere.
// ---------------------------------------------------------------------------
__global__ __launch_bounds__(256, 2)
void softnn_main_kernel(const float* __restrict__ X, const float* __restrict__ Pm,
                        const float* __restrict__ Qm, const float* __restrict__ Mm) {
    __shared__ float As[BK][BM + PAD];
    __shared__ float Bs[BK][BN + PAD];

    const int rowTile = blockIdx.x;            // 0..31
    const int cb      = blockIdx.y;            // 0..191

    const float* Y; const float* y2g; float coef; float* target; int colBase;
    if (cb < 32)      { Y = Pm; y2g = g_p2; coef = 4.0f; target = g_Spos; colBase = cb * BN; }
    else if (cb < 64) { Y = Qm; y2g = g_q2; coef = 4.0f; target = g_Sden; colBase = (cb - 32) * BN; }
    else              { Y = Mm; y2g = g_m2; coef = 2.0f; target = g_Sden; colBase = (cb - 64) * BN; }

    const int tid = threadIdx.x;
    const int tx  = tid & 15;          // 0..15 -> 8 columns each
    const int ty  = tid >> 4;          // 0..15 -> 8 rows each
    const int rowBase = rowTile * BM;

    // loader mapping: 256 threads, each loads 4 float4 (one per pass)
    const int lr = tid >> 3;           // 0..31 : row within 32-row pass
    const int lk = (tid & 7) * 4;      // 0,4,...,28 : k offset

    float acc[8][8];
    #pragma unroll
    for (int i = 0; i < 8; i++)
        #pragma unroll
        for (int j = 0; j < 8; j++) acc[i][j] = 0.0f;

    #pragma unroll
    for (int kb = 0; kb < DIM; kb += BK) {
        #pragma unroll
        for (int p = 0; p < 4; ++p) {
            int r = lr + p * 32;
            float4 va = *(const float4*)&X[(size_t)(rowBase + r) * DIM + kb + lk];
            As[lk + 0][r] = va.x; As[lk + 1][r] = va.y;
            As[lk + 2][r] = va.z; As[lk + 3][r] = va.w;
            float4 vb = *(const float4*)&Y[(size_t)(colBase + r) * DIM + kb + lk];
            Bs[lk + 0][r] = vb.x; Bs[lk + 1][r] = vb.y;
            Bs[lk + 2][r] = vb.z; Bs[lk + 3][r] = vb.w;
        }
        __syncthreads();

        #pragma unroll
        for (int k = 0; k < BK; ++k) {
            float a[8], b[8];
            *(float4*)&a[0] = *(const float4*)&As[k][ty * 8];
            *(float4*)&a[4] = *(const float4*)&As[k][ty * 8 + 4];
            *(float4*)&b[0] = *(const float4*)&Bs[k][tx * 8];
            *(float4*)&b[4] = *(const float4*)&Bs[k][tx * 8 + 4];
            #pragma unroll
            for (int i = 0; i < 8; i++)
                #pragma unroll
                for (int j = 0; j < 8; j++)
                    acc[i][j] = fmaf(a[i], b[j], acc[i][j]);
        }
        __syncthreads();
    }

    // Epilogue: d = sqrt(max(x2 + y2 - 2*dot, 0)); accumulate exp(-coef*d)
    float x2v[8], y2v[8];
    #pragma unroll
    for (int i = 0; i < 8; i++) x2v[i] = g_x2[rowBase + ty * 8 + i];
    #pragma unroll
    for (int j = 0; j < 8; j++) y2v[j] = y2g[colBase + tx * 8 + j];

    const float nc = -coef * 1.4426950408889634f;   // -coef * log2(e)
    float rowsum[8];
    #pragma unroll
    for (int i = 0; i < 8; i++) rowsum[i] = 0.0f;

    #pragma unroll
    for (int i = 0; i < 8; i++) {
        #pragma unroll
        for (int j = 0; j < 8; j++) {
            float sq = fmaf(-2.0f, acc[i][j], x2v[i] + y2v[j]);
            sq = fmaxf(sq, 0.0f);
            float d = sqrt_approx(sq);
            rowsum[i] += ex2_approx(nc * d);
        }
    }

    // Reduce across the 16 threads (tx) that share each row; xor masks 1,2,4,8
    // stay inside each 16-lane half-warp (same ty).
    #pragma unroll
    for (int i = 0; i < 8; i++) {
        float s = rowsum[i];
        s += __shfl_xor_sync(0xFFFFFFFFu, s, 1);
        s += __shfl_xor_sync(0xFFFFFFFFu, s, 2);
        s += __shfl_xor_sync(0xFFFFFFFFu, s, 4);
        s += __shfl_xor_sync(0xFFFFFFFFu, s, 8);
        if (tx == 0) atomicAdd(&target[rowBase + ty * 8 + i], s);
    }
}

// ---------------------------------------------------------------------------
// Kernel 3: loss = sum_i ( log(Sden[i]) - log(Spos[i]) )
// ---------------------------------------------------------------------------
__global__ void final_kernel(float* __restrict__ out) {
    __shared__ double sm[256];
    int tid = threadIdx.x;
    double acc = 0.0;
    for (int i = tid; i < N_IMG; i += 256)
        acc += (double)(logf(g_Sden[i]) - logf(g_Spos[i]));
    sm[tid] = acc;
    __syncthreads();
    for (int o = 128; o > 0; o >>= 1) {
        if (tid < o) sm[tid] += sm[tid + o];
        __syncthreads();
    }
    if (tid == 0) out[0] = (float)sm[0];
}

// ---------------------------------------------------------------------------
extern "C" void kernel_launch(void* const* d_in, const int* in_sizes, int n_in,
                              void* d_out, int out_size) {
    const float* X = (const float*)d_in[0];   // image_views    [4096,128]
    const float* P = (const float*)d_in[1];   // positive_views [4096,128]
    const float* Q = (const float*)d_in[2];   // negative_views [4096,128]
    const float* M = (const float*)d_in[3];   // other_embeddings [16384,128]

    // 28672 rows total, one warp per row, 8 warps per block
    prep_kernel<<<(N_IMG + N_POS + N_NEG + N_OTH) / 8, 256>>>(X, P, Q, M);

    dim3 grid(N_IMG / BM, (N_POS + N_NEG + N_OTH) / BN);   // 32 x 192
    softnn_main_kernel<<<grid, 256>>>(X, P, Q, M);

    final_kernel<<<1, 256>>>((float*)d_out);
}

// round 7
// speedup vs baseline: 2.8264x; 2.8246x over previous
#include <cuda_runtime.h>
#include <stdint.h>

// ---------------------------------------------------------------------------
// Problem constants
// ---------------------------------------------------------------------------
#define N_IMG  4096
#define N_YTOT 24576                 // P(4096) + Q(4096) + M(16384) concatenated
#define DIM    128

#define TILE          128            // square M/N tile
#define N_COL_TILES   (N_YTOT / TILE)          // 192
#define N_GROUPS      4
#define TILES_PER_CTA (N_COL_TILES / N_GROUPS) // 48
#define LDW           132            // padded smem row length in words (128+4)
#define TILE_WORDS    (TILE * LDW)   // 16896 words per 128x128 tile
#define SMEM_BYTES    (3 * TILE_WORDS * 4)   // A + 2 B buffers = 202752 B

// Segment boundaries in 128-wide col-tile numbering:
//   tiles [0,32)   = P  -> sumP, coef 4
//   tiles [32,64)  = Q  -> sumD, coef 4
//   tiles [64,192) = M  -> sumD, coef 2
#define P_TILE_END 32
#define Q_TILE_END 64

// ---------------------------------------------------------------------------
// Device-global scratch (no allocation allowed)
// ---------------------------------------------------------------------------
__device__ float g_Ar[N_IMG * DIM];      // X rounded to tf32
__device__ float g_Yr[N_YTOT * DIM];     // [P;Q;M] rounded to tf32
__device__ float g_x2[N_IMG];            // exact fp32 squared norms
__device__ float g_y2[N_YTOT];
__device__ float g_Spos[N_IMG];
__device__ float g_Sden[N_IMG];

// ---------------------------------------------------------------------------
// Helpers
// ---------------------------------------------------------------------------
__device__ __forceinline__ float ex2_approx(float x) {
    float r; asm("ex2.approx.f32 %0, %1;" : "=f"(r) : "f"(x)); return r;
}
__device__ __forceinline__ float sqrt_approx(float x) {
    float r; asm("sqrt.approx.f32 %0, %1;" : "=f"(r) : "f"(x)); return r;
}
__device__ __forceinline__ uint32_t smem_u32(const void* p) {
    uint32_t a;
    asm("{ .reg .u64 t; cvta.to.shared.u64 t, %1; cvt.u32.u64 %0, t; }" : "=r"(a) : "l"(p));
    return a;
}
__device__ __forceinline__ uint32_t f2tf32(float x) {
    uint32_t r; asm("cvt.rna.tf32.f32 %0, %1;" : "=r"(r) : "f"(x)); return r;
}

#define CP16(dst, src) \
    asm volatile("cp.async.cg.shared.global [%0], [%1], 16;" :: "r"((uint32_t)(dst)), "l"(src) : "memory")
#define CP_COMMIT()   asm volatile("cp.async.commit_group;" ::: "memory")
#define CP_WAIT(n)    asm volatile("cp.async.wait_group %0;" :: "n"(n) : "memory")

// m16n8k8 tf32 mma: D += A*B, A row-major (4 regs), B col-major (2 regs)
#define MMA_TF32(c, a, b)                                                     \
    asm volatile("mma.sync.aligned.m16n8k8.row.col.f32.tf32.tf32.f32 "        \
        "{%0,%1,%2,%3}, {%4,%5,%6,%7}, {%8,%9}, {%0,%1,%2,%3};"               \
        : "+f"((c)[0]), "+f"((c)[1]), "+f"((c)[2]), "+f"((c)[3])              \
        : "r"((a)[0]), "r"((a)[1]), "r"((a)[2]), "r"((a)[3]),                 \
          "r"((b)[0]), "r"((b)[1]))

// ---------------------------------------------------------------------------
// Kernel 1: tf32-round all inputs into scratch + exact squared norms + zero accs.
// One warp per row (128 floats = 1 float4 per lane).
// ---------------------------------------------------------------------------
__global__ void prep_kernel(const float* __restrict__ X, const float* __restrict__ P,
                            const float* __restrict__ Q, const float* __restrict__ M) {
    int gwarp = (blockIdx.x * blockDim.x + threadIdx.x) >> 5;
    int lane  = threadIdx.x & 31;
    const float* src; float* nrm; float* dstR;
    if (gwarp < N_IMG) {
        src = X + (size_t)gwarp * DIM;  nrm = g_x2 + gwarp;  dstR = g_Ar + (size_t)gwarp * DIM;
    } else {
        int yr = gwarp - N_IMG;
        if (yr < 4096)       src = P + (size_t)yr * DIM;
        else if (yr < 8192)  src = Q + (size_t)(yr - 4096) * DIM;
        else                 src = M + (size_t)(yr - 8192) * DIM;
        nrm = g_y2 + yr;  dstR = g_Yr + (size_t)yr * DIM;
    }

    float4 v = ((const float4*)src)[lane];
    float s = v.x * v.x + v.y * v.y + v.z * v.z + v.w * v.w;
    uint4 r;
    r.x = f2tf32(v.x); r.y = f2tf32(v.y); r.z = f2tf32(v.z); r.w = f2tf32(v.w);
    ((uint4*)dstR)[lane] = r;

    #pragma unroll
    for (int o = 16; o > 0; o >>= 1) s += __shfl_xor_sync(0xFFFFFFFFu, s, o);
    if (lane == 0) {
        *nrm = s;
        if (gwarp < N_IMG) { g_Spos[gwarp] = 0.0f; g_Sden[gwarp] = 0.0f; }
    }
}

// ---------------------------------------------------------------------------
// Load a 128x128 fp32 tile (row stride DIM) into padded smem (row stride LDW).
// 256 threads, 16 x 16B chunks each, coalesced.
// ---------------------------------------------------------------------------
__device__ __forceinline__ void load_tile(uint32_t sb, int wordOff, const float* src, int tid) {
    #pragma unroll
    for (int it = 0; it < 16; ++it) {
        int idx = it * 256 + tid;
        int row = idx >> 5;           // 0..127
        int ch  = idx & 31;           // 16B chunk within row
        uint32_t dst = sb + (uint32_t)(wordOff * 4 + row * (LDW * 4) + ch * 16);
        CP16(dst, src + (size_t)row * DIM + ch * 4);
    }
}

// ---------------------------------------------------------------------------
// Kernel 2: persistent-A tf32 mma.sync GEMM with fused exp-distance epilogue.
// grid = (4 groups, 32 rowTiles) = 128 CTAs, 1/SM. 8 warps, warp tile 64x32.
// Each CTA streams its group's 48 col tiles through a 2-buffer cp.async ring.
// ---------------------------------------------------------------------------
__global__ __launch_bounds__(256, 1)
void softnn_mma_kernel() {
    extern __shared__ float smem[];
    const uint32_t sb = smem_u32(smem);
    const uint32_t* smw = (const uint32_t*)smem;

    const int tid  = threadIdx.x;
    const int wid  = tid >> 5;
    const int lane = tid & 31;
    const int gid  = lane >> 2;          // 0..7
    const int tig  = lane & 3;           // 0..3
    const int warpM = wid >> 2;          // 0..1 -> 64-row halves
    const int warpN = wid & 3;           // 0..3 -> 32-col quarters
    const int mbase = warpM * 64;
    const int nbase = warpN * 32;

    const int g       = blockIdx.x;               // column group 0..3
    const int rowBase = blockIdx.y * TILE;        // 0..31 row tiles

    // Prologue: A tile + first two B tiles
    load_tile(sb, 0,              g_Ar + (size_t)rowBase * DIM, tid);
    load_tile(sb, TILE_WORDS,     g_Yr + (size_t)(g * TILES_PER_CTA + 0) * TILE * DIM, tid);
    CP_COMMIT();                                  // group: {A, B(t0)}
    load_tile(sb, 2 * TILE_WORDS, g_Yr + (size_t)(g * TILES_PER_CTA + 1) * TILE * DIM, tid);
    CP_COMMIT();                                  // group: {B(t1)}

    float x2r[8];
    #pragma unroll
    for (int i = 0; i < 4; ++i) {
        x2r[2*i]   = g_x2[rowBase + mbase + i * 16 + gid];
        x2r[2*i+1] = g_x2[rowBase + mbase + i * 16 + gid + 8];
    }

    float sumP[8], sumD[8], acc[4][4][4];
    #pragma unroll
    for (int r = 0; r < 8; ++r) { sumP[r] = 0.0f; sumD[r] = 0.0f; }
    #pragma unroll
    for (int i = 0; i < 4; ++i)
        #pragma unroll
        for (int j = 0; j < 4; ++j)
            #pragma unroll
            for (int c = 0; c < 4; ++c) acc[i][j][c] = 0.0f;

    for (int t = 0; t < TILES_PER_CTA; ++t) {
        CP_WAIT(1);                 // current tile's buffer ready
        __syncthreads();

        const uint32_t* A = smw;
        const uint32_t* B = smw + (1 + (t & 1)) * TILE_WORDS;

        // ---- GEMM: 16 k-steps of m16n8k8 ----
        #pragma unroll 4
        for (int ks = 0; ks < 16; ++ks) {
            const int k0 = ks * 8;
            uint32_t Af[4][4], Bf[4][2];
            #pragma unroll
            for (int i = 0; i < 4; ++i) {
                const uint32_t* p = A + (mbase + i * 16 + gid) * LDW + k0 + tig;
                Af[i][0] = p[0]; Af[i][1] = p[8 * LDW]; Af[i][2] = p[4]; Af[i][3] = p[8 * LDW + 4];
            }
            #pragma unroll
            for (int j = 0; j < 4; ++j) {
                const uint32_t* p = B + (nbase + j * 8 + gid) * LDW + k0 + tig;
                Bf[j][0] = p[0]; Bf[j][1] = p[4];
            }
            #pragma unroll
            for (int i = 0; i < 4; ++i)
                #pragma unroll
                for (int j = 0; j < 4; ++j)
                    MMA_TF32(acc[i][j], Af[i], Bf[j]);
        }
        __syncthreads();            // all warps done reading buf[t&1]

        // Prefetch tile t+2 into the buffer just freed (overlaps epilogue + next GEMM)
        if (t + 2 < TILES_PER_CTA)
            load_tile(sb, (1 + (t & 1)) * TILE_WORDS,
                      g_Yr + (size_t)(g * TILES_PER_CTA + t + 2) * TILE * DIM, tid);
        CP_COMMIT();                // commit even when empty to keep group accounting

        // ---- Epilogue: d = sqrt(max(x2+y2-2dot,0)); sum exp(-coef*d) ----
        const int gt      = g * TILES_PER_CTA + t;   // global col tile 0..191
        const int colBase = gt * TILE;
        const float nc = (gt < Q_TILE_END) ? -5.7707801635558537f    // -4*log2(e)  (P,Q)
                                           : -2.8853900817779268f;   // -2*log2(e)  (M)
        float tsum[8];
        #pragma unroll
        for (int r = 0; r < 8; ++r) tsum[r] = 0.0f;

        #pragma unroll
        for (int j = 0; j < 4; ++j) {
            const int n0 = colBase + nbase + j * 8 + 2 * tig;
            const float y0 = __ldg(&g_y2[n0]);
            const float y1 = __ldg(&g_y2[n0 + 1]);
            #pragma unroll
            for (int i = 0; i < 4; ++i) {
                float s00 = fmaxf(fmaf(-2.0f, acc[i][j][0], x2r[2*i]   + y0), 0.0f);
                float s01 = fmaxf(fmaf(-2.0f, acc[i][j][1], x2r[2*i]   + y1), 0.0f);
                float s10 = fmaxf(fmaf(-2.0f, acc[i][j][2], x2r[2*i+1] + y0), 0.0f);
                float s11 = fmaxf(fmaf(-2.0f, acc[i][j][3], x2r[2*i+1] + y1), 0.0f);
                tsum[2*i]   += ex2_approx(nc * sqrt_approx(s00)) + ex2_approx(nc * sqrt_approx(s01));
                tsum[2*i+1] += ex2_approx(nc * sqrt_approx(s10)) + ex2_approx(nc * sqrt_approx(s11));
                acc[i][j][0] = 0.0f; acc[i][j][1] = 0.0f;
                acc[i][j][2] = 0.0f; acc[i][j][3] = 0.0f;
            }
        }
        if (gt < P_TILE_END) {
            #pragma unroll
            for (int r = 0; r < 8; ++r) sumP[r] += tsum[r];
        } else {
            #pragma unroll
            for (int r = 0; r < 8; ++r) sumD[r] += tsum[r];
        }
    }

    // Column reduce within 4-lane groups (lanes sharing the same rows), then atomics.
    #pragma unroll
    for (int r = 0; r < 8; ++r) {
        float p = sumP[r], d = sumD[r];
        p += __shfl_xor_sync(0xFFFFFFFFu, p, 1);
        p += __shfl_xor_sync(0xFFFFFFFFu, p, 2);
        d += __shfl_xor_sync(0xFFFFFFFFu, d, 1);
        d += __shfl_xor_sync(0xFFFFFFFFu, d, 2);
        if (tig == 0) {
            int row = rowBase + mbase + (r >> 1) * 16 + gid + (r & 1) * 8;
            atomicAdd(&g_Spos[row], p);
            atomicAdd(&g_Sden[row], d);
        }
    }
}

// ---------------------------------------------------------------------------
// Kernel 3: loss = sum_i ( log(Sden[i]) - log(Spos[i]) )
// ---------------------------------------------------------------------------
__global__ void final_kernel(float* __restrict__ out) {
    __shared__ double sm[256];
    int tid = threadIdx.x;
    double acc = 0.0;
    for (int i = tid; i < N_IMG; i += 256)
        acc += (double)(logf(g_Sden[i]) - logf(g_Spos[i]));
    sm[tid] = acc;
    __syncthreads();
    for (int o = 128; o > 0; o >>= 1) {
        if (tid < o) sm[tid] += sm[tid + o];
        __syncthreads();
    }
    if (tid == 0) out[0] = (float)sm[0];
}

// ---------------------------------------------------------------------------
extern "C" void kernel_launch(void* const* d_in, const int* in_sizes, int n_in,
                              void* d_out, int out_size) {
    const float* X = (const float*)d_in[0];   // image_views      [4096,128]
    const float* P = (const float*)d_in[1];   // positive_views   [4096,128]
    const float* Q = (const float*)d_in[2];   // negative_views   [4096,128]
    const float* M = (const float*)d_in[3];   // other_embeddings [16384,128]

    cudaFuncSetAttribute(softnn_mma_kernel,
                         cudaFuncAttributeMaxDynamicSharedMemorySize, SMEM_BYTES);

    // 28672 rows, one warp per row, 8 warps per block
    prep_kernel<<<(N_IMG + N_YTOT) / 8, 256>>>(X, P, Q, M);

    dim3 grid(N_GROUPS, N_IMG / TILE);       // 4 x 32 = 128 CTAs
    softnn_mma_kernel<<<grid, 256, SMEM_BYTES>>>();

    final_kernel<<<1, 256>>>((float*)d_out);
}

// round 8
// speedup vs baseline: 4.3366x; 1.5343x over previous
#include <cuda_runtime.h>
#include <cuda_bf16.h>
#include <stdint.h>

// ---------------------------------------------------------------------------
// Problem constants
// ---------------------------------------------------------------------------
#define N_IMG  4096
#define N_YTOT 24576                 // P(4096) + Q(4096) + M(16384) concatenated
#define DIM    128

#define TILE          128            // square M/N tile
#define N_COL_TILES   (N_YTOT / TILE)          // 192
#define N_GROUPS      4
#define TILES_PER_CTA (N_COL_TILES / N_GROUPS) // 48

#define LDWRD         68             // padded smem row stride in 32-bit words (64+4)
#define TILE_SMB      (TILE * LDWRD * 4)       // 34816 bytes per 128x128 bf16 tile
#define TILE_SMW      (TILE * LDWRD)           // 8704 words
#define SMEM_BYTES    (4 * TILE_SMB)           // A + 3 B buffers = 139264 B

// Segment boundaries in 128-wide col-tile numbering:
//   [0,32) = P -> sumP coef 4 ; [32,64) = Q -> sumD coef 4 ; [64,192) = M -> sumD coef 2
#define P_TILE_END 32
#define Q_TILE_END 64

// ---------------------------------------------------------------------------
// Device-global scratch (no allocation allowed)
// ---------------------------------------------------------------------------
__device__ __nv_bfloat16 g_Ab[N_IMG * DIM];    // X as bf16
__device__ __nv_bfloat16 g_Yb[N_YTOT * DIM];   // [P;Q;M] as bf16
__device__ float g_x2[N_IMG];                  // exact fp32 squared norms
__device__ float g_y2[N_YTOT];
__device__ float g_Spos[N_IMG];
__device__ float g_Sden[N_IMG];

// ---------------------------------------------------------------------------
// Helpers
// ---------------------------------------------------------------------------
__device__ __forceinline__ float ex2_approx(float x) {
    float r; asm("ex2.approx.f32 %0, %1;" : "=f"(r) : "f"(x)); return r;
}
__device__ __forceinline__ float sqrt_approx(float x) {
    float r; asm("sqrt.approx.f32 %0, %1;" : "=f"(r) : "f"(x)); return r;
}
__device__ __forceinline__ uint32_t smem_u32(const void* p) {
    uint32_t a;
    asm("{ .reg .u64 t; cvta.to.shared.u64 t, %1; cvt.u32.u64 %0, t; }" : "=r"(a) : "l"(p));
    return a;
}

#define CP16(dst, src) \
    asm volatile("cp.async.cg.shared.global [%0], [%1], 16;" :: "r"((uint32_t)(dst)), "l"(src) : "memory")
#define CP_COMMIT()   asm volatile("cp.async.commit_group;" ::: "memory")
#define CP_WAIT(n)    asm volatile("cp.async.wait_group %0;" :: "n"(n) : "memory")

// m16n8k16 bf16 mma: D += A*B, A row-major (4 regs = 8 bf16), B col-major (2 regs)
#define MMA_BF16(c, a, b)                                                     \
    asm volatile("mma.sync.aligned.m16n8k16.row.col.f32.bf16.bf16.f32 "       \
        "{%0,%1,%2,%3}, {%4,%5,%6,%7}, {%8,%9}, {%0,%1,%2,%3};"               \
        : "+f"((c)[0]), "+f"((c)[1]), "+f"((c)[2]), "+f"((c)[3])              \
        : "r"((a)[0]), "r"((a)[1]), "r"((a)[2]), "r"((a)[3]),                 \
          "r"((b)[0]), "r"((b)[1]))

// ---------------------------------------------------------------------------
// Kernel 1: bf16-convert all inputs into scratch + exact fp32 squared norms.
// One warp per row (128 floats = 1 float4 per lane).
// ---------------------------------------------------------------------------
__global__ void prep_kernel(const float* __restrict__ X, const float* __restrict__ P,
                            const float* __restrict__ Q, const float* __restrict__ M) {
    int gwarp = (blockIdx.x * blockDim.x + threadIdx.x) >> 5;
    int lane  = threadIdx.x & 31;
    const float* src; float* nrm; __nv_bfloat16* dstB;
    if (gwarp < N_IMG) {
        src = X + (size_t)gwarp * DIM;  nrm = g_x2 + gwarp;  dstB = g_Ab + (size_t)gwarp * DIM;
    } else {
        int yr = gwarp - N_IMG;
        if (yr < 4096)       src = P + (size_t)yr * DIM;
        else if (yr < 8192)  src = Q + (size_t)(yr - 4096) * DIM;
        else                 src = M + (size_t)(yr - 8192) * DIM;
        nrm = g_y2 + yr;  dstB = g_Yb + (size_t)yr * DIM;
    }

    float4 v = ((const float4*)src)[lane];
    float s = v.x * v.x + v.y * v.y + v.z * v.z + v.w * v.w;
    __nv_bfloat162 lo = __floats2bfloat162_rn(v.x, v.y);   // .x = low half
    __nv_bfloat162 hi = __floats2bfloat162_rn(v.z, v.w);
    uint2 packed = make_uint2(*(uint32_t*)&lo, *(uint32_t*)&hi);
    ((uint2*)dstB)[lane] = packed;

    #pragma unroll
    for (int o = 16; o > 0; o >>= 1) s += __shfl_xor_sync(0xFFFFFFFFu, s, o);
    if (lane == 0) {
        *nrm = s;
        if (gwarp < N_IMG) { g_Spos[gwarp] = 0.0f; g_Sden[gwarp] = 0.0f; }
    }
}

// ---------------------------------------------------------------------------
// Load a 128x128 bf16 tile (row = 256B) into padded smem (row = 272B).
// 2048 16B chunks over 256 threads = 8 each, coalesced.
// ---------------------------------------------------------------------------
__device__ __forceinline__ void load_tile(uint32_t sb, uint32_t byteOff,
                                          const __nv_bfloat16* src, int tid) {
    #pragma unroll
    for (int it = 0; it < 8; ++it) {
        int idx = it * 256 + tid;
        int row = idx >> 4;           // 0..127
        int ch  = idx & 15;           // 16B chunk within 256B row
        CP16(sb + byteOff + (uint32_t)(row * 272 + ch * 16),
             src + (size_t)row * DIM + ch * 8);
    }
}

// ---------------------------------------------------------------------------
// GEMM for one 128x128x128 tile: 8 k-steps of m16n8k16 bf16, warp tile 64x32.
// ---------------------------------------------------------------------------
__device__ __forceinline__ void gemm_tile(float acc[4][4][4],
                                          const uint32_t* __restrict__ A,
                                          const uint32_t* __restrict__ B,
                                          int mbase, int nbase, int gid, int tig) {
    #pragma unroll
    for (int ks = 0; ks < 8; ++ks) {
        const int kw = ks * 8;        // 16 bf16 = 8 words per k-step
        uint32_t Af[4][4], Bf[4][2];
        #pragma unroll
        for (int i = 0; i < 4; ++i) {
            const uint32_t* p = A + (mbase + i * 16 + gid) * LDWRD + kw + tig;
            Af[i][0] = p[0]; Af[i][1] = p[8 * LDWRD];
            Af[i][2] = p[4]; Af[i][3] = p[8 * LDWRD + 4];
        }
        #pragma unroll
        for (int j = 0; j < 4; ++j) {
            const uint32_t* p = B + (nbase + j * 8 + gid) * LDWRD + kw + tig;
            Bf[j][0] = p[0]; Bf[j][1] = p[4];
        }
        #pragma unroll
        for (int i = 0; i < 4; ++i)
            #pragma unroll
            for (int j = 0; j < 4; ++j)
                MMA_BF16(acc[i][j], Af[i], Bf[j]);
    }
}

// ---------------------------------------------------------------------------
// Epilogue for one tile's accumulators: d=sqrt(max(x2+y2-2dot,0)),
// accumulate exp2(nc*d), then zero acc for reuse.
// ---------------------------------------------------------------------------
__device__ __forceinline__ void epi_tile(float acc[4][4][4], int gt,
                                         const float* __restrict__ x2r,
                                         float* __restrict__ sumP, float* __restrict__ sumD,
                                         int nbase, int tig) {
    const int colBase = gt * TILE;
    const float nc = (gt < Q_TILE_END) ? -5.7707801635558537f    // -4*log2(e)  (P,Q)
                                       : -2.8853900817779268f;   // -2*log2(e)  (M)
    float tsum[8];
    #pragma unroll
    for (int r = 0; r < 8; ++r) tsum[r] = 0.0f;

    #pragma unroll
    for (int j = 0; j < 4; ++j) {
        const int n0 = colBase + nbase + j * 8 + 2 * tig;
        const float y0 = __ldg(&g_y2[n0]);
        const float y1 = __ldg(&g_y2[n0 + 1]);
        #pragma unroll
        for (int i = 0; i < 4; ++i) {
            float s00 = fmaxf(fmaf(-2.0f, acc[i][j][0], x2r[2*i]   + y0), 0.0f);
            float s01 = fmaxf(fmaf(-2.0f, acc[i][j][1], x2r[2*i]   + y1), 0.0f);
            float s10 = fmaxf(fmaf(-2.0f, acc[i][j][2], x2r[2*i+1] + y0), 0.0f);
            float s11 = fmaxf(fmaf(-2.0f, acc[i][j][3], x2r[2*i+1] + y1), 0.0f);
            tsum[2*i]   += ex2_approx(nc * sqrt_approx(s00)) + ex2_approx(nc * sqrt_approx(s01));
            tsum[2*i+1] += ex2_approx(nc * sqrt_approx(s10)) + ex2_approx(nc * sqrt_approx(s11));
            acc[i][j][0] = 0.0f; acc[i][j][1] = 0.0f;
            acc[i][j][2] = 0.0f; acc[i][j][3] = 0.0f;
        }
    }
    if (gt < P_TILE_END) {
        #pragma unroll
        for (int r = 0; r < 8; ++r) sumP[r] += tsum[r];
    } else {
        #pragma unroll
        for (int r = 0; r < 8; ++r) sumD[r] += tsum[r];
    }
}

// ---------------------------------------------------------------------------
// Kernel 2: persistent-A bf16 mma.sync GEMM, fused epilogue pipelined one tile
// behind the GEMM (two accumulator banks; tensor and MUFU pipes overlap).
// grid = (4 groups, 32 rowTiles) = 128 CTAs, 1/SM. 8 warps, warp tile 64x32.
// ---------------------------------------------------------------------------
__global__ __launch_bounds__(256, 1)
void softnn_mma_kernel() {
    extern __shared__ float smem[];
    const uint32_t sb = smem_u32(smem);
    const uint32_t* smw = (const uint32_t*)smem;

    const int tid  = threadIdx.x;
    const int wid  = tid >> 5;
    const int lane = tid & 31;
    const int gid  = lane >> 2;          // 0..7
    const int tig  = lane & 3;           // 0..3
    const int mbase = (wid >> 2) * 64;   // 64-row halves
    const int nbase = (wid & 3) * 32;    // 32-col quarters

    const int g       = blockIdx.x;               // column group 0..3
    const int rowBase = blockIdx.y * TILE;        // row tile base
    const __nv_bfloat16* Ybase = g_Yb + (size_t)(g * TILES_PER_CTA) * TILE * DIM;

    // Prologue: A tile + first two B tiles into a 3-buffer ring
    load_tile(sb, 0,            g_Ab + (size_t)rowBase * DIM, tid);
    load_tile(sb, TILE_SMB,     Ybase, tid);
    CP_COMMIT();                                  // g0 = {A, B0}
    load_tile(sb, 2 * TILE_SMB, Ybase + (size_t)TILE * DIM, tid);
    CP_COMMIT();                                  // g1 = {B1}

    float x2r[8];
    #pragma unroll
    for (int i = 0; i < 4; ++i) {
        x2r[2*i]   = g_x2[rowBase + mbase + i * 16 + gid];
        x2r[2*i+1] = g_x2[rowBase + mbase + i * 16 + gid + 8];
    }

    float sumP[8], sumD[8], accA[4][4][4], accB[4][4][4];
    #pragma unroll
    for (int r = 0; r < 8; ++r) { sumP[r] = 0.0f; sumD[r] = 0.0f; }
    #pragma unroll
    for (int i = 0; i < 4; ++i)
        #pragma unroll
        for (int j = 0; j < 4; ++j)
            #pragma unroll
            for (int c = 0; c < 4; ++c) { accA[i][j][c] = 0.0f; accB[i][j][c] = 0.0f; }

    const uint32_t* Aw = smw;

    for (int t = 0; t < TILES_PER_CTA; t += 2) {
        // ---- even tile t -> accA; epilogue of tile t-1 from accB ----
        CP_WAIT(1);                  // B(t) landed
        __syncthreads();             // everyone done reading buffer (t+2)%3's old tile
        if (t + 2 < TILES_PER_CTA)
            load_tile(sb, (1 + (t + 2) % 3) * TILE_SMB,
                      Ybase + (size_t)(t + 2) * TILE * DIM, tid);
        CP_COMMIT();
        gemm_tile(accA, Aw, smw + (1 + t % 3) * TILE_SMW, mbase, nbase, gid, tig);
        if (t > 0)
            epi_tile(accB, g * TILES_PER_CTA + t - 1, x2r, sumP, sumD, nbase, tig);

        // ---- odd tile t+1 -> accB; epilogue of tile t from accA ----
        CP_WAIT(1);                  // B(t+1) landed
        __syncthreads();
        if (t + 3 < TILES_PER_CTA)
            load_tile(sb, (1 + (t + 3) % 3) * TILE_SMB,
                      Ybase + (size_t)(t + 3) * TILE * DIM, tid);
        CP_COMMIT();
        gemm_tile(accB, Aw, smw + (1 + (t + 1) % 3) * TILE_SMW, mbase, nbase, gid, tig);
        epi_tile(accA, g * TILES_PER_CTA + t, x2r, sumP, sumD, nbase, tig);
    }
    // Final epilogue: tile 47 lives in accB
    epi_tile(accB, g * TILES_PER_CTA + TILES_PER_CTA - 1, x2r, sumP, sumD, nbase, tig);

    // Column reduce within 4-lane groups (lanes sharing the same rows), then atomics.
    #pragma unroll
    for (int r = 0; r < 8; ++r) {
        float p = sumP[r], d = sumD[r];
        p += __shfl_xor_sync(0xFFFFFFFFu, p, 1);
        p += __shfl_xor_sync(0xFFFFFFFFu, p, 2);
        d += __shfl_xor_sync(0xFFFFFFFFu, d, 1);
        d += __shfl_xor_sync(0xFFFFFFFFu, d, 2);
        if (tig == 0) {
            int row = rowBase + mbase + (r >> 1) * 16 + gid + (r & 1) * 8;
            atomicAdd(&g_Spos[row], p);
            atomicAdd(&g_Sden[row], d);
        }
    }
}

// ---------------------------------------------------------------------------
// Kernel 3: loss = sum_i ( log(Sden[i]) - log(Spos[i]) )
// ---------------------------------------------------------------------------
__global__ void final_kernel(float* __restrict__ out) {
    __shared__ double sm[256];
    int tid = threadIdx.x;
    double acc = 0.0;
    for (int i = tid; i < N_IMG; i += 256)
        acc += (double)(logf(g_Sden[i]) - logf(g_Spos[i]));
    sm[tid] = acc;
    __syncthreads();
    for (int o = 128; o > 0; o >>= 1) {
        if (tid < o) sm[tid] += sm[tid + o];
        __syncthreads();
    }
    if (tid == 0) out[0] = (float)sm[0];
}

// ---------------------------------------------------------------------------
extern "C" void kernel_launch(void* const* d_in, const int* in_sizes, int n_in,
                              void* d_out, int out_size) {
    const float* X = (const float*)d_in[0];   // image_views      [4096,128]
    const float* P = (const float*)d_in[1];   // positive_views   [4096,128]
    const float* Q = (const float*)d_in[2];   // negative_views   [4096,128]
    const float* M = (const float*)d_in[3];   // other_embeddings [16384,128]

    cudaFuncSetAttribute(softnn_mma_kernel,
                         cudaFuncAttributeMaxDynamicSharedMemorySize, SMEM_BYTES);

    // 28672 rows, one warp per row, 8 warps per block
    prep_kernel<<<(N_IMG + N_YTOT) / 8, 256>>>(X, P, Q, M);

    dim3 grid(N_GROUPS, N_IMG / TILE);       // 4 x 32 = 128 CTAs
    softnn_mma_kernel<<<grid, 256, SMEM_BYTES>>>();

    final_kernel<<<1, 256>>>((float*)d_out);
}

// round 9
// speedup vs baseline: 4.4607x; 1.0286x over previous
#include <cuda_runtime.h>
#include <cuda_bf16.h>
#include <stdint.h>

// ---------------------------------------------------------------------------
// Problem constants
// ---------------------------------------------------------------------------
#define N_IMG  4096
#define N_YTOT 24576                 // P(4096) + Q(4096) + M(16384) concatenated
#define DIM    128

#define TILE        128              // square M/N tile
#define N_COL_TILES 192              // 24576 / 128
#define N_ROW_TILES 32               // 4096 / 128
#define STRIP       6                // col tiles per strip
#define STRIPS_PER_ROW (N_COL_TILES / STRIP)       // 32
#define N_STRIPS    (N_ROW_TILES * STRIPS_PER_ROW) // 1024
#define GRID_CTAS   148              // one CTA per SM

#define LDWRD       68               // padded smem row stride in words (64+4)
#define TILE_SMB    (TILE * LDWRD * 4)   // 34816 B per 128x128 bf16 tile
#define TILE_SMW    (TILE * LDWRD)       // 8704 words
// smem: A0,A1 (parity ring) + B0,B1,B2 (3-ring) + x2 stage (2*128 floats)
#define SMEM_BYTES  (5 * TILE_SMB + 2 * TILE * 4)

// Segment boundaries in 128-wide col-tile numbering:
//   [0,32) = P -> sumP coef 4 ; [32,64) = Q -> sumD coef 4 ; [64,192) = M -> sumD coef 2
#define P_TILE_END 32
#define Q_TILE_END 64

// ---------------------------------------------------------------------------
// Device-global scratch (no allocation allowed)
// ---------------------------------------------------------------------------
__device__ __nv_bfloat16 g_Ab[N_IMG * DIM];    // X as bf16
__device__ __nv_bfloat16 g_Yb[N_YTOT * DIM];   // [P;Q;M] as bf16
__device__ float g_x2[N_IMG];                  // exact fp32 squared norms
__device__ float g_y2[N_YTOT];
__device__ float g_Spos[N_IMG];
__device__ float g_Sden[N_IMG];

// ---------------------------------------------------------------------------
// Helpers
// ---------------------------------------------------------------------------
__device__ __forceinline__ float ex2_approx(float x) {
    float r; asm("ex2.approx.f32 %0, %1;" : "=f"(r) : "f"(x)); return r;
}
__device__ __forceinline__ float sqrt_approx(float x) {
    float r; asm("sqrt.approx.f32 %0, %1;" : "=f"(r) : "f"(x)); return r;
}
__device__ __forceinline__ uint32_t smem_u32(const void* p) {
    uint32_t a;
    asm("{ .reg .u64 t; cvta.to.shared.u64 t, %1; cvt.u32.u64 %0, t; }" : "=r"(a) : "l"(p));
    return a;
}

#define CP16(dst, src) \
    asm volatile("cp.async.cg.shared.global [%0], [%1], 16;" :: "r"((uint32_t)(dst)), "l"(src) : "memory")
#define CP_COMMIT()   asm volatile("cp.async.commit_group;" ::: "memory")
#define CP_WAIT(n)    asm volatile("cp.async.wait_group %0;" :: "n"(n) : "memory")

// m16n8k16 bf16 mma: D += A*B, A row-major (4 regs = 8 bf16), B col-major (2 regs)
#define MMA_BF16(c, a, b)                                                     \
    asm volatile("mma.sync.aligned.m16n8k16.row.col.f32.bf16.bf16.f32 "       \
        "{%0,%1,%2,%3}, {%4,%5,%6,%7}, {%8,%9}, {%0,%1,%2,%3};"               \
        : "+f"((c)[0]), "+f"((c)[1]), "+f"((c)[2]), "+f"((c)[3])              \
        : "r"((a)[0]), "r"((a)[1]), "r"((a)[2]), "r"((a)[3]),                 \
          "r"((b)[0]), "r"((b)[1]))

// ---------------------------------------------------------------------------
// Kernel 1: bf16-convert all inputs into scratch + exact fp32 squared norms.
// One warp per row (128 floats = 1 float4 per lane).
// ---------------------------------------------------------------------------
__global__ void prep_kernel(const float* __restrict__ X, const float* __restrict__ P,
                            const float* __restrict__ Q, const float* __restrict__ M) {
    int gwarp = (blockIdx.x * blockDim.x + threadIdx.x) >> 5;
    int lane  = threadIdx.x & 31;
    const float* src; float* nrm; __nv_bfloat16* dstB;
    if (gwarp < N_IMG) {
        src = X + (size_t)gwarp * DIM;  nrm = g_x2 + gwarp;  dstB = g_Ab + (size_t)gwarp * DIM;
    } else {
        int yr = gwarp - N_IMG;
        if (yr < 4096)       src = P + (size_t)yr * DIM;
        else if (yr < 8192)  src = Q + (size_t)(yr - 4096) * DIM;
        else                 src = M + (size_t)(yr - 8192) * DIM;
        nrm = g_y2 + yr;  dstB = g_Yb + (size_t)yr * DIM;
    }

    float4 v = ((const float4*)src)[lane];
    float s = v.x * v.x + v.y * v.y + v.z * v.z + v.w * v.w;
    __nv_bfloat162 lo = __floats2bfloat162_rn(v.x, v.y);
    __nv_bfloat162 hi = __floats2bfloat162_rn(v.z, v.w);
    uint2 packed = make_uint2(*(uint32_t*)&lo, *(uint32_t*)&hi);
    ((uint2*)dstB)[lane] = packed;

    #pragma unroll
    for (int o = 16; o > 0; o >>= 1) s += __shfl_xor_sync(0xFFFFFFFFu, s, o);
    if (lane == 0) {
        *nrm = s;
        if (gwarp < N_IMG) { g_Spos[gwarp] = 0.0f; g_Sden[gwarp] = 0.0f; }
    }
}

// ---------------------------------------------------------------------------
// Load a 128x128 bf16 tile (row = 256B) into padded smem (row = 272B).
// ---------------------------------------------------------------------------
__device__ __forceinline__ void load_tile(uint32_t sb, uint32_t byteOff,
                                          const __nv_bfloat16* src, int tid) {
    #pragma unroll
    for (int it = 0; it < 8; ++it) {
        int idx = it * 256 + tid;
        int row = idx >> 4;
        int ch  = idx & 15;
        CP16(sb + byteOff + (uint32_t)(row * 272 + ch * 16),
             src + (size_t)row * DIM + ch * 8);
    }
}

// Issue loads for flat-list tile n: B tile always; A tile when n starts a strip.
__device__ __forceinline__ void issue_loads(uint32_t sb, int s0, int L, int n, int tid) {
    if (n >= L) return;
    const int ns = s0 + n / STRIP;
    if ((n % STRIP) == 0)
        load_tile(sb, (uint32_t)(((n / STRIP) & 1) * TILE_SMB),
                  g_Ab + (size_t)(ns >> 5) * TILE * DIM, tid);
    const int gct = (ns & (STRIPS_PER_ROW - 1)) * STRIP + n % STRIP;
    load_tile(sb, (uint32_t)((2 + n % 3) * TILE_SMB),
              g_Yb + (size_t)gct * TILE * DIM, tid);
}

// ---------------------------------------------------------------------------
// GEMM for one 128x128x128 tile: 8 k-steps of m16n8k16 bf16, warp tile 64x32.
// ---------------------------------------------------------------------------
__device__ __forceinline__ void gemm_tile(float acc[4][4][4],
                                          const uint32_t* __restrict__ A,
                                          const uint32_t* __restrict__ B,
                                          int mbase, int nbase, int gid, int tig) {
    #pragma unroll
    for (int ks = 0; ks < 8; ++ks) {
        const int kw = ks * 8;
        uint32_t Af[4][4], Bf[4][2];
        #pragma unroll
        for (int i = 0; i < 4; ++i) {
            const uint32_t* p = A + (mbase + i * 16 + gid) * LDWRD + kw + tig;
            Af[i][0] = p[0]; Af[i][1] = p[8 * LDWRD];
            Af[i][2] = p[4]; Af[i][3] = p[8 * LDWRD + 4];
        }
        #pragma unroll
        for (int j = 0; j < 4; ++j) {
            const uint32_t* p = B + (nbase + j * 8 + gid) * LDWRD + kw + tig;
            Bf[j][0] = p[0]; Bf[j][1] = p[4];
        }
        #pragma unroll
        for (int i = 0; i < 4; ++i)
            #pragma unroll
            for (int j = 0; j < 4; ++j)
                MMA_BF16(acc[i][j], Af[i], Bf[j]);
    }
}

// ---------------------------------------------------------------------------
// Epilogue: d=sqrt(max(x2+y2-2dot,0)); accumulate exp2(nc*d); zero acc.
// x2 comes from an smem stage (per-strip parity buffer).
// ---------------------------------------------------------------------------
__device__ __forceinline__ void epi_tile(float acc[4][4][4], int gt,
                                         const float* __restrict__ x2s,
                                         float* __restrict__ sumP, float* __restrict__ sumD,
                                         int mbase, int nbase, int gid, int tig) {
    float x2v[8];
    #pragma unroll
    for (int i = 0; i < 4; ++i) {
        x2v[2*i]   = x2s[mbase + i * 16 + gid];
        x2v[2*i+1] = x2s[mbase + i * 16 + gid + 8];
    }
    const int colBase = gt * TILE;
    const float nc = (gt < Q_TILE_END) ? -5.7707801635558537f    // -4*log2(e)  (P,Q)
                                       : -2.8853900817779268f;   // -2*log2(e)  (M)
    float tsum[8];
    #pragma unroll
    for (int r = 0; r < 8; ++r) tsum[r] = 0.0f;

    #pragma unroll
    for (int j = 0; j < 4; ++j) {
        const int n0 = colBase + nbase + j * 8 + 2 * tig;
        const float y0 = __ldg(&g_y2[n0]);
        const float y1 = __ldg(&g_y2[n0 + 1]);
        #pragma unroll
        for (int i = 0; i < 4; ++i) {
            float s00 = fmaxf(fmaf(-2.0f, acc[i][j][0], x2v[2*i]   + y0), 0.0f);
            float s01 = fmaxf(fmaf(-2.0f, acc[i][j][1], x2v[2*i]   + y1), 0.0f);
            float s10 = fmaxf(fmaf(-2.0f, acc[i][j][2], x2v[2*i+1] + y0), 0.0f);
            float s11 = fmaxf(fmaf(-2.0f, acc[i][j][3], x2v[2*i+1] + y1), 0.0f);
            tsum[2*i]   += ex2_approx(nc * sqrt_approx(s00)) + ex2_approx(nc * sqrt_approx(s01));
            tsum[2*i+1] += ex2_approx(nc * sqrt_approx(s10)) + ex2_approx(nc * sqrt_approx(s11));
            acc[i][j][0] = 0.0f; acc[i][j][1] = 0.0f;
            acc[i][j][2] = 0.0f; acc[i][j][3] = 0.0f;
        }
    }
    if (gt < P_TILE_END) {
        #pragma unroll
        for (int r = 0; r < 8; ++r) sumP[r] += tsum[r];
    } else {
        #pragma unroll
        for (int r = 0; r < 8; ++r) sumD[r] += tsum[r];
    }
}

// Flush per-row sums to global accumulators and reset them.
__device__ __forceinline__ void flush_sums(int rowTileBase,
                                           float* __restrict__ sumP, float* __restrict__ sumD,
                                           int mbase, int gid, int tig) {
    #pragma unroll
    for (int r = 0; r < 8; ++r) {
        float p = sumP[r], d = sumD[r];
        p += __shfl_xor_sync(0xFFFFFFFFu, p, 1);
        p += __shfl_xor_sync(0xFFFFFFFFu, p, 2);
        d += __shfl_xor_sync(0xFFFFFFFFu, d, 1);
        d += __shfl_xor_sync(0xFFFFFFFFu, d, 2);
        if (tig == 0) {
            int row = rowTileBase + mbase + (r >> 1) * 16 + gid + (r & 1) * 8;
            atomicAdd(&g_Spos[row], p);
            atomicAdd(&g_Sden[row], d);
        }
        sumP[r] = 0.0f; sumD[r] = 0.0f;
    }
}

// ---------------------------------------------------------------------------
// One pipeline step: GEMM tile m into CUR, epilogue of tile m-1 from PREV.
// ---------------------------------------------------------------------------
#define STEP(m_, CUR, PREV) do {                                              \
    const int m = (m_);                                                       \
    CP_WAIT(1);                                                               \
    __syncthreads();                                                          \
    issue_loads(sb, s0, L, m + 2, tid);                                       \
    CP_COMMIT();                                                              \
    if ((m % STRIP) == 0) {                                                   \
        const int p   = (m / STRIP) & 1;                                      \
        const int row = (s0 + m / STRIP) >> 5;                                \
        if (tid < TILE) x2s[p * TILE + tid] = g_x2[row * TILE + tid];         \
    }                                                                         \
    gemm_tile(CUR, smw + ((m / STRIP) & 1) * TILE_SMW,                        \
              smw + (2 + m % 3) * TILE_SMW, mbase, nbase, gid, tig);          \
    if (m > 0) {                                                              \
        const int e  = m - 1;                                                 \
        const int es = s0 + e / STRIP;                                        \
        const int er = es >> 5;                                               \
        if (er != curRow) {                                                   \
            flush_sums(curRow * TILE, sumP, sumD, mbase, gid, tig);           \
            curRow = er;                                                      \
        }                                                                     \
        epi_tile(PREV, (es & (STRIPS_PER_ROW - 1)) * STRIP + e % STRIP,       \
                 x2s + ((e / STRIP) & 1) * TILE,                              \
                 sumP, sumD, mbase, nbase, gid, tig);                         \
    }                                                                         \
} while (0)

// ---------------------------------------------------------------------------
// Kernel 2: persistent bf16 mma.sync GEMM over strip-partitioned tile space.
// 148 CTAs (one per SM); each handles 6-7 strips of 6 col tiles. A is
// double-buffered per strip, B triple-buffered per tile, epilogue pipelined
// one tile behind the GEMM across strip boundaries.
// ---------------------------------------------------------------------------
__global__ __launch_bounds__(256, 1)
void softnn_mma_kernel() {
    extern __shared__ float smem[];
    const uint32_t sb = smem_u32(smem);
    const uint32_t* smw = (const uint32_t*)smem;
    float* x2s = smem + 5 * TILE_SMW;            // 2 x 128 floats

    const int tid  = threadIdx.x;
    const int wid  = tid >> 5;
    const int lane = tid & 31;
    const int gid  = lane >> 2;
    const int tig  = lane & 3;
    const int mbase = (wid >> 2) * 64;
    const int nbase = (wid & 3) * 32;

    const int c  = blockIdx.x;
    const int s0 = (c * N_STRIPS) / GRID_CTAS;
    const int s1 = ((c + 1) * N_STRIPS) / GRID_CTAS;
    const int L  = (s1 - s0) * STRIP;            // 36 or 42 tiles (always even)

    // Pre-issue tiles 0 and 1 (tile 0 carries its strip's A load)
    issue_loads(sb, s0, L, 0, tid); CP_COMMIT();
    issue_loads(sb, s0, L, 1, tid); CP_COMMIT();

    float sumP[8], sumD[8], accA[4][4][4], accB[4][4][4];
    #pragma unroll
    for (int r = 0; r < 8; ++r) { sumP[r] = 0.0f; sumD[r] = 0.0f; }
    #pragma unroll
    for (int i = 0; i < 4; ++i)
        #pragma unroll
        for (int j = 0; j < 4; ++j)
            #pragma unroll
            for (int k = 0; k < 4; ++k) { accA[i][j][k] = 0.0f; accB[i][j][k] = 0.0f; }

    int curRow = s0 >> 5;

    for (int t = 0; t < L; t += 2) {
        STEP(t,     accA, accB);
        STEP(t + 1, accB, accA);
    }

    // Final epilogue: tile L-1 (odd index -> accB)
    {
        const int e  = L - 1;
        const int es = s0 + e / STRIP;
        const int er = es >> 5;
        if (er != curRow) {
            flush_sums(curRow * TILE, sumP, sumD, mbase, gid, tig);
            curRow = er;
        }
        epi_tile(accB, (es & (STRIPS_PER_ROW - 1)) * STRIP + e % STRIP,
                 x2s + ((e / STRIP) & 1) * TILE,
                 sumP, sumD, mbase, nbase, gid, tig);
        flush_sums(curRow * TILE, sumP, sumD, mbase, gid, tig);
    }
}

// ---------------------------------------------------------------------------
// Kernel 3: loss = sum_i ( log(Sden[i]) - log(Spos[i]) )
// ---------------------------------------------------------------------------
__global__ void final_kernel(float* __restrict__ out) {
    __shared__ double sm[256];
    int tid = threadIdx.x;
    double acc = 0.0;
    for (int i = tid; i < N_IMG; i += 256)
        acc += (double)(logf(g_Sden[i]) - logf(g_Spos[i]));
    sm[tid] = acc;
    __syncthreads();
    for (int o = 128; o > 0; o >>= 1) {
        if (tid < o) sm[tid] += sm[tid + o];
        __syncthreads();
    }
    if (tid == 0) out[0] = (float)sm[0];
}

// ---------------------------------------------------------------------------
extern "C" void kernel_launch(void* const* d_in, const int* in_sizes, int n_in,
                              void* d_out, int out_size) {
    const float* X = (const float*)d_in[0];   // image_views      [4096,128]
    const float* P = (const float*)d_in[1];   // positive_views   [4096,128]
    const float* Q = (const float*)d_in[2];   // negative_views   [4096,128]
    const float* M = (const float*)d_in[3];   // other_embeddings [16384,128]

    cudaFuncSetAttribute(softnn_mma_kernel,
                         cudaFuncAttributeMaxDynamicSharedMemorySize, SMEM_BYTES);

    // 28672 rows, one warp per row, 8 warps per block
    prep_kernel<<<(N_IMG + N_YTOT) / 8, 256>>>(X, P, Q, M);

    softnn_mma_kernel<<<GRID_CTAS, 256, SMEM_BYTES>>>();

    final_kernel<<<1, 256>>>((float*)d_out);
}

// round 10
// speedup vs baseline: 4.6891x; 1.0512x over previous
#include <cuda_runtime.h>
#include <cuda_bf16.h>
#include <stdint.h>

// ---------------------------------------------------------------------------
// Problem constants
// ---------------------------------------------------------------------------
#define N_IMG  4096
#define N_YTOT 24576                 // P(4096) + Q(4096) + M(16384) concatenated
#define DIM    128

#define TILE        128              // square M/N tile
#define N_COL_TILES 192              // 24576 / 128
#define N_ROW_TILES 32               // 4096 / 128
#define STRIP       6                // col tiles per strip
#define STRIPS_PER_ROW (N_COL_TILES / STRIP)       // 32
#define N_STRIPS    (N_ROW_TILES * STRIPS_PER_ROW) // 1024
#define GRID_CTAS   148              // one CTA per SM

#define LDWRD       68               // padded smem row stride in words (64+4)
#define TILE_SMB    (TILE * LDWRD * 4)   // 34816 B per 128x128 bf16 tile
#define TILE_SMW    (TILE * LDWRD)       // 8704 words
// smem: A0,A1 (parity ring) + B0,B1,B2 (3-ring) + x2 stage (2*128 floats)
#define SMEM_BYTES  (5 * TILE_SMB + 2 * TILE * 4)

// Segment boundaries in 128-wide col-tile numbering:
//   [0,32) = P -> sumP coef 4 ; [32,64) = Q -> sumD coef 4 ; [64,192) = M -> sumD coef 2
#define P_TILE_END 32
#define Q_TILE_END 64

// ---------------------------------------------------------------------------
// Device-global scratch (no allocation allowed)
// ---------------------------------------------------------------------------
__device__ __nv_bfloat16 g_Ab[N_IMG * DIM];    // X as bf16
__device__ __nv_bfloat16 g_Yb[N_YTOT * DIM];   // [P;Q;M] as bf16
__device__ float g_x2[N_IMG];                  // exact fp32 squared norms
__device__ float g_y2[N_YTOT];
__device__ float g_Spos[N_IMG];
__device__ float g_Sden[N_IMG];

// ---------------------------------------------------------------------------
// Helpers
// ---------------------------------------------------------------------------
__device__ __forceinline__ float ex2_approx(float x) {
    float r; asm("ex2.approx.f32 %0, %1;" : "=f"(r) : "f"(x)); return r;
}
__device__ __forceinline__ float sqrt_approx(float x) {
    float r; asm("sqrt.approx.f32 %0, %1;" : "=f"(r) : "f"(x)); return r;
}
__device__ __forceinline__ uint32_t smem_u32(const void* p) {
    uint32_t a;
    asm("{ .reg .u64 t; cvta.to.shared.u64 t, %1; cvt.u32.u64 %0, t; }" : "=r"(a) : "l"(p));
    return a;
}

#define CP16(dst, src) \
    asm volatile("cp.async.cg.shared.global [%0], [%1], 16;" :: "r"((uint32_t)(dst)), "l"(src) : "memory")
#define CP_COMMIT()   asm volatile("cp.async.commit_group;" ::: "memory")
#define CP_WAIT(n)    asm volatile("cp.async.wait_group %0;" :: "n"(n) : "memory")

// m16n8k16 bf16 mma: D += A*B, A row-major (4 regs = 8 bf16), B col-major (2 regs)
#define MMA_BF16(c, a, b)                                                     \
    asm volatile("mma.sync.aligned.m16n8k16.row.col.f32.bf16.bf16.f32 "       \
        "{%0,%1,%2,%3}, {%4,%5,%6,%7}, {%8,%9}, {%0,%1,%2,%3};"               \
        : "+f"((c)[0]), "+f"((c)[1]), "+f"((c)[2]), "+f"((c)[3])              \
        : "r"((a)[0]), "r"((a)[1]), "r"((a)[2]), "r"((a)[3]),                 \
          "r"((b)[0]), "r"((b)[1]))

// ---------------------------------------------------------------------------
// Kernel 1: bf16-convert all inputs into scratch + exact fp32 squared norms.
// ---------------------------------------------------------------------------
__global__ void prep_kernel(const float* __restrict__ X, const float* __restrict__ P,
                            const float* __restrict__ Q, const float* __restrict__ M) {
    int gwarp = (blockIdx.x * blockDim.x + threadIdx.x) >> 5;
    int lane  = threadIdx.x & 31;
    const float* src; float* nrm; __nv_bfloat16* dstB;
    if (gwarp < N_IMG) {
        src = X + (size_t)gwarp * DIM;  nrm = g_x2 + gwarp;  dstB = g_Ab + (size_t)gwarp * DIM;
    } else {
        int yr = gwarp - N_IMG;
        if (yr < 4096)       src = P + (size_t)yr * DIM;
        else if (yr < 8192)  src = Q + (size_t)(yr - 4096) * DIM;
        else                 src = M + (size_t)(yr - 8192) * DIM;
        nrm = g_y2 + yr;  dstB = g_Yb + (size_t)yr * DIM;
    }

    float4 v = ((const float4*)src)[lane];
    float s = v.x * v.x + v.y * v.y + v.z * v.z + v.w * v.w;
    __nv_bfloat162 lo = __floats2bfloat162_rn(v.x, v.y);
    __nv_bfloat162 hi = __floats2bfloat162_rn(v.z, v.w);
    uint2 packed = make_uint2(*(uint32_t*)&lo, *(uint32_t*)&hi);
    ((uint2*)dstB)[lane] = packed;

    #pragma unroll
    for (int o = 16; o > 0; o >>= 1) s += __shfl_xor_sync(0xFFFFFFFFu, s, o);
    if (lane == 0) {
        *nrm = s;
        if (gwarp < N_IMG) { g_Spos[gwarp] = 0.0f; g_Sden[gwarp] = 0.0f; }
    }
}

// ---------------------------------------------------------------------------
// Load a 128x128 bf16 tile (row = 256B) into padded smem (row = 272B).
// ---------------------------------------------------------------------------
__device__ __forceinline__ void load_tile(uint32_t sb, uint32_t byteOff,
                                          const __nv_bfloat16* src, int tid) {
    #pragma unroll
    for (int it = 0; it < 8; ++it) {
        int idx = it * 256 + tid;
        int row = idx >> 4;
        int ch  = idx & 15;
        CP16(sb + byteOff + (uint32_t)(row * 272 + ch * 16),
             src + (size_t)row * DIM + ch * 8);
    }
}

// Issue loads for flat-list tile n: B tile always; A tile when n starts a strip.
__device__ __forceinline__ void issue_loads(uint32_t sb, int s0, int L, int n, int tid) {
    if (n >= L) return;
    const int ns = s0 + n / STRIP;
    if ((n % STRIP) == 0)
        load_tile(sb, (uint32_t)(((n / STRIP) & 1) * TILE_SMB),
                  g_Ab + (size_t)(ns >> 5) * TILE * DIM, tid);
    const int gct = (ns & (STRIPS_PER_ROW - 1)) * STRIP + n % STRIP;
    load_tile(sb, (uint32_t)((2 + n % 3) * TILE_SMB),
              g_Yb + (size_t)gct * TILE * DIM, tid);
}

// ---------------------------------------------------------------------------
// Fused tile step: GEMM of the current tile into accC, with the PREVIOUS
// tile's epilogue (from accP) interleaved one j-chunk per odd k-step so
// MUFU/FMA work issues while the tensor pipe drains the MMAs.
// ---------------------------------------------------------------------------
__device__ __forceinline__ void gemm_epi_tile(
    float accC[4][4][4], float accP[4][4][4], int doEpi, int gtPrev,
    const uint32_t* __restrict__ A, const uint32_t* __restrict__ B,
    const float* __restrict__ x2sPrev,
    float* __restrict__ sumP, float* __restrict__ sumD,
    int mbase, int nbase, int gid, int tig)
{
    const float nc = (gtPrev < Q_TILE_END) ? -5.7707801635558537f   // -4*log2(e)
                                           : -2.8853900817779268f;  // -2*log2(e)
    float x2v[8], tsum[8];
    #pragma unroll
    for (int r = 0; r < 8; ++r) tsum[r] = 0.0f;
    if (doEpi) {
        #pragma unroll
        for (int i = 0; i < 4; ++i) {
            x2v[2*i]   = x2sPrev[mbase + i * 16 + gid];
            x2v[2*i+1] = x2sPrev[mbase + i * 16 + gid + 8];
        }
    }

    #pragma unroll
    for (int ks = 0; ks < 8; ++ks) {
        const int kw = ks * 8;
        uint32_t Af[4][4], Bf[4][2];
        #pragma unroll
        for (int i = 0; i < 4; ++i) {
            const uint32_t* p = A + (mbase + i * 16 + gid) * LDWRD + kw + tig;
            Af[i][0] = p[0]; Af[i][1] = p[8 * LDWRD];
            Af[i][2] = p[4]; Af[i][3] = p[8 * LDWRD + 4];
        }
        #pragma unroll
        for (int j = 0; j < 4; ++j) {
            const uint32_t* p = B + (nbase + j * 8 + gid) * LDWRD + kw + tig;
            Bf[j][0] = p[0]; Bf[j][1] = p[4];
        }
        #pragma unroll
        for (int i = 0; i < 4; ++i)
            #pragma unroll
            for (int j = 0; j < 4; ++j)
                MMA_BF16(accC[i][j], Af[i], Bf[j]);

        // One epilogue j-chunk of the previous tile per odd k-step.
        if (ks & 1) {
            const int j = ks >> 1;
            if (doEpi) {
                const int n0 = gtPrev * TILE + nbase + j * 8 + 2 * tig;
                const float y0 = __ldg(&g_y2[n0]);
                const float y1 = __ldg(&g_y2[n0 + 1]);
                #pragma unroll
                for (int i = 0; i < 4; ++i) {
                    float s00 = fmaxf(fmaf(-2.0f, accP[i][j][0], x2v[2*i]   + y0), 0.0f);
                    float s01 = fmaxf(fmaf(-2.0f, accP[i][j][1], x2v[2*i]   + y1), 0.0f);
                    float s10 = fmaxf(fmaf(-2.0f, accP[i][j][2], x2v[2*i+1] + y0), 0.0f);
                    float s11 = fmaxf(fmaf(-2.0f, accP[i][j][3], x2v[2*i+1] + y1), 0.0f);
                    tsum[2*i]   += ex2_approx(nc * sqrt_approx(s00)) + ex2_approx(nc * sqrt_approx(s01));
                    tsum[2*i+1] += ex2_approx(nc * sqrt_approx(s10)) + ex2_approx(nc * sqrt_approx(s11));
                    accP[i][j][0] = 0.0f; accP[i][j][1] = 0.0f;
                    accP[i][j][2] = 0.0f; accP[i][j][3] = 0.0f;
                }
            }
        }
    }

    if (doEpi) {
        if (gtPrev < P_TILE_END) {
            #pragma unroll
            for (int r = 0; r < 8; ++r) sumP[r] += tsum[r];
        } else {
            #pragma unroll
            for (int r = 0; r < 8; ++r) sumD[r] += tsum[r];
        }
    }
}

// ---------------------------------------------------------------------------
// Standalone epilogue (used once for the final tile).
// ---------------------------------------------------------------------------
__device__ __forceinline__ void epi_tile(float acc[4][4][4], int gt,
                                         const float* __restrict__ x2s,
                                         float* __restrict__ sumP, float* __restrict__ sumD,
                                         int mbase, int nbase, int gid, int tig) {
    float x2v[8];
    #pragma unroll
    for (int i = 0; i < 4; ++i) {
        x2v[2*i]   = x2s[mbase + i * 16 + gid];
        x2v[2*i+1] = x2s[mbase + i * 16 + gid + 8];
    }
    const float nc = (gt < Q_TILE_END) ? -5.7707801635558537f
                                       : -2.8853900817779268f;
    float tsum[8];
    #pragma unroll
    for (int r = 0; r < 8; ++r) tsum[r] = 0.0f;

    #pragma unroll
    for (int j = 0; j < 4; ++j) {
        const int n0 = gt * TILE + nbase + j * 8 + 2 * tig;
        const float y0 = __ldg(&g_y2[n0]);
        const float y1 = __ldg(&g_y2[n0 + 1]);
        #pragma unroll
        for (int i = 0; i < 4; ++i) {
            float s00 = fmaxf(fmaf(-2.0f, acc[i][j][0], x2v[2*i]   + y0), 0.0f);
            float s01 = fmaxf(fmaf(-2.0f, acc[i][j][1], x2v[2*i]   + y1), 0.0f);
            float s10 = fmaxf(fmaf(-2.0f, acc[i][j][2], x2v[2*i+1] + y0), 0.0f);
            float s11 = fmaxf(fmaf(-2.0f, acc[i][j][3], x2v[2*i+1] + y1), 0.0f);
            tsum[2*i]   += ex2_approx(nc * sqrt_approx(s00)) + ex2_approx(nc * sqrt_approx(s01));
            tsum[2*i+1] += ex2_approx(nc * sqrt_approx(s10)) + ex2_approx(nc * sqrt_approx(s11));
        }
    }
    if (gt < P_TILE_END) {
        #pragma unroll
        for (int r = 0; r < 8; ++r) sumP[r] += tsum[r];
    } else {
        #pragma unroll
        for (int r = 0; r < 8; ++r) sumD[r] += tsum[r];
    }
}

// Flush per-row sums to global accumulators and reset them.
__device__ __forceinline__ void flush_sums(int rowTileBase,
                                           float* __restrict__ sumP, float* __restrict__ sumD,
                                           int mbase, int gid, int tig) {
    #pragma unroll
    for (int r = 0; r < 8; ++r) {
        float p = sumP[r], d = sumD[r];
        p += __shfl_xor_sync(0xFFFFFFFFu, p, 1);
        p += __shfl_xor_sync(0xFFFFFFFFu, p, 2);
        d += __shfl_xor_sync(0xFFFFFFFFu, d, 1);
        d += __shfl_xor_sync(0xFFFFFFFFu, d, 2);
        if (tig == 0) {
            int row = rowTileBase + mbase + (r >> 1) * 16 + gid + (r & 1) * 8;
            atomicAdd(&g_Spos[row], p);
            atomicAdd(&g_Sden[row], d);
        }
        sumP[r] = 0.0f; sumD[r] = 0.0f;
    }
}

// ---------------------------------------------------------------------------
// One pipeline step: GEMM tile m into CUR with interleaved epilogue of
// tile m-1 from PREV.
// ---------------------------------------------------------------------------
#define STEP(m_, CUR, PREV) do {                                              \
    const int m = (m_);                                                       \
    CP_WAIT(1);                                                               \
    __syncthreads();                                                          \
    issue_loads(sb, s0, L, m + 2, tid);                                       \
    CP_COMMIT();                                                              \
    if ((m % STRIP) == 0) {                                                   \
        const int p   = (m / STRIP) & 1;                                      \
        const int row = (s0 + m / STRIP) >> 5;                                \
        if (tid < TILE) x2s[p * TILE + tid] = g_x2[row * TILE + tid];         \
    }                                                                         \
    int gtPrev = 0, doEpi = (m > 0);                                          \
    const float* x2p = x2s;                                                   \
    if (doEpi) {                                                              \
        const int e  = m - 1;                                                 \
        const int es = s0 + e / STRIP;                                        \
        const int er = es >> 5;                                               \
        if (er != curRow) {                                                   \
            flush_sums(curRow * TILE, sumP, sumD, mbase, gid, tig);           \
            curRow = er;                                                      \
        }                                                                     \
        gtPrev = (es & (STRIPS_PER_ROW - 1)) * STRIP + e % STRIP;             \
        x2p = x2s + ((e / STRIP) & 1) * TILE;                                 \
    }                                                                         \
    gemm_epi_tile(CUR, PREV, doEpi, gtPrev,                                   \
                  smw + ((m / STRIP) & 1) * TILE_SMW,                         \
                  smw + (2 + m % 3) * TILE_SMW,                               \
                  x2p, sumP, sumD, mbase, nbase, gid, tig);                   \
} while (0)

// ---------------------------------------------------------------------------
// Kernel 2: persistent bf16 mma.sync GEMM over strip-partitioned tile space.
// 148 CTAs; epilogue of tile t-1 interleaved into tile t's k-loop.
// ---------------------------------------------------------------------------
__global__ __launch_bounds__(256, 1)
void softnn_mma_kernel() {
    extern __shared__ float smem[];
    const uint32_t sb = smem_u32(smem);
    const uint32_t* smw = (const uint32_t*)smem;
    float* x2s = smem + 5 * TILE_SMW;            // 2 x 128 floats

    const int tid  = threadIdx.x;
    const int wid  = tid >> 5;
    const int lane = tid & 31;
    const int gid  = lane >> 2;
    const int tig  = lane & 3;
    const int mbase = (wid >> 2) * 64;
    const int nbase = (wid & 3) * 32;

    const int c  = blockIdx.x;
    const int s0 = (c * N_STRIPS) / GRID_CTAS;
    const int s1 = ((c + 1) * N_STRIPS) / GRID_CTAS;
    const int L  = (s1 - s0) * STRIP;            // 36 or 42 tiles (always even)

    issue_loads(sb, s0, L, 0, tid); CP_COMMIT();
    issue_loads(sb, s0, L, 1, tid); CP_COMMIT();

    float sumP[8], sumD[8], accA[4][4][4], accB[4][4][4];
    #pragma unroll
    for (int r = 0; r < 8; ++r) { sumP[r] = 0.0f; sumD[r] = 0.0f; }
    #pragma unroll
    for (int i = 0; i < 4; ++i)
        #pragma unroll
        for (int j = 0; j < 4; ++j)
            #pragma unroll
            for (int k = 0; k < 4; ++k) { accA[i][j][k] = 0.0f; accB[i][j][k] = 0.0f; }

    int curRow = s0 >> 5;

    for (int t = 0; t < L; t += 2) {
        STEP(t,     accA, accB);
        STEP(t + 1, accB, accA);
    }

    // Final epilogue: tile L-1 (odd index -> accB)
    {
        const int e  = L - 1;
        const int es = s0 + e / STRIP;
        const int er = es >> 5;
        if (er != curRow) {
            flush_sums(curRow * TILE, sumP, sumD, mbase, gid, tig);
            curRow = er;
        }
        epi_tile(accB, (es & (STRIPS_PER_ROW - 1)) * STRIP + e % STRIP,
                 x2s + ((e / STRIP) & 1) * TILE,
                 sumP, sumD, mbase, nbase, gid, tig);
        flush_sums(curRow * TILE, sumP, sumD, mbase, gid, tig);
    }
}

// ---------------------------------------------------------------------------
// Kernel 3: loss = sum_i ( log(Sden[i]) - log(Spos[i]) )
// ---------------------------------------------------------------------------
__global__ void final_kernel(float* __restrict__ out) {
    __shared__ double sm[256];
    int tid = threadIdx.x;
    double acc = 0.0;
    for (int i = tid; i < N_IMG; i += 256)
        acc += (double)(logf(g_Sden[i]) - logf(g_Spos[i]));
    sm[tid] = acc;
    __syncthreads();
    for (int o = 128; o > 0; o >>= 1) {
        if (tid < o) sm[tid] += sm[tid + o];
        __syncthreads();
    }
    if (tid == 0) out[0] = (float)sm[0];
}

// ---------------------------------------------------------------------------
extern "C" void kernel_launch(void* const* d_in, const int* in_sizes, int n_in,
                              void* d_out, int out_size) {
    const float* X = (const float*)d_in[0];   // image_views      [4096,128]
    const float* P = (const float*)d_in[1];   // positive_views   [4096,128]
    const float* Q = (const float*)d_in[2];   // negative_views   [4096,128]
    const float* M = (const float*)d_in[3];   // other_embeddings [16384,128]

    cudaFuncSetAttribute(softnn_mma_kernel,
                         cudaFuncAttributeMaxDynamicSharedMemorySize, SMEM_BYTES);

    prep_kernel<<<(N_IMG + N_YTOT) / 8, 256>>>(X, P, Q, M);

    softnn_mma_kernel<<<GRID_CTAS, 256, SMEM_BYTES>>>();

    final_kernel<<<1, 256>>>((float*)d_out);
}

// round 11
// speedup vs baseline: 4.6972x; 1.0017x over previous
#include <cuda_runtime.h>
#include <cuda_bf16.h>
#include <stdint.h>

// ---------------------------------------------------------------------------
// Problem constants
// ---------------------------------------------------------------------------
#define N_IMG  4096
#define N_YTOT 24576                 // P(4096) + Q(4096) + M(16384) concatenated
#define DIM    128

#define TILE          128            // square M/N tile
#define N_GROUPS      4              // column groups (grid.x)
#define TILES_PER_CTA 48             // 192 col tiles / 4 groups
#define TILES_PER_WG  24             // tiles per warp-group (even/odd split)

#define LDWRD       68               // padded smem row stride in words (64+4)
#define TILE_SMB    (TILE * LDWRD * 4)   // 34816 B per 128x128 bf16 tile
#define TILE_SMW    (TILE * LDWRD)       // 8704 words
// smem: A + 4 B buffers (2 per warp-group)
#define SMEM_BYTES  (5 * TILE_SMB)       // 174080 B

// Segment boundaries in 128-wide col-tile numbering:
//   [0,32) = P -> sumP coef 4 ; [32,64) = Q -> sumD coef 4 ; [64,192) = M -> sumD coef 2
#define P_TILE_END 32
#define Q_TILE_END 64

// ---------------------------------------------------------------------------
// Device-global scratch (no allocation allowed)
// ---------------------------------------------------------------------------
__device__ __nv_bfloat16 g_Ab[N_IMG * DIM];    // X as bf16
__device__ __nv_bfloat16 g_Yb[N_YTOT * DIM];   // [P;Q;M] as bf16
__device__ float g_x2[N_IMG];                  // exact fp32 squared norms
__device__ float g_y2[N_YTOT];
__device__ float g_Spos[N_IMG];
__device__ float g_Sden[N_IMG];

// ---------------------------------------------------------------------------
// Helpers
// ---------------------------------------------------------------------------
__device__ __forceinline__ float ex2_approx(float x) {
    float r; asm("ex2.approx.f32 %0, %1;" : "=f"(r) : "f"(x)); return r;
}
__device__ __forceinline__ float sqrt_approx(float x) {
    float r; asm("sqrt.approx.f32 %0, %1;" : "=f"(r) : "f"(x)); return r;
}
__device__ __forceinline__ uint32_t smem_u32(const void* p) {
    uint32_t a;
    asm("{ .reg .u64 t; cvta.to.shared.u64 t, %1; cvt.u32.u64 %0, t; }" : "=r"(a) : "l"(p));
    return a;
}

#define CP16(dst, src) \
    asm volatile("cp.async.cg.shared.global [%0], [%1], 16;" :: "r"((uint32_t)(dst)), "l"(src) : "memory")
#define CP_COMMIT()   asm volatile("cp.async.commit_group;" ::: "memory")
#define CP_WAIT(n)    asm volatile("cp.async.wait_group %0;" :: "n"(n) : "memory")

// Named barrier per warp-group (128 threads). Ids 1/2 (0 belongs to syncthreads).
#define BARG(g) asm volatile("bar.sync %0, 128;" :: "r"(1 + (g)) : "memory")

// m16n8k16 bf16 mma: D += A*B, A row-major (4 regs = 8 bf16), B col-major (2 regs)
#define MMA_BF16(c, a, b)                                                     \
    asm volatile("mma.sync.aligned.m16n8k16.row.col.f32.bf16.bf16.f32 "       \
        "{%0,%1,%2,%3}, {%4,%5,%6,%7}, {%8,%9}, {%0,%1,%2,%3};"               \
        : "+f"((c)[0]), "+f"((c)[1]), "+f"((c)[2]), "+f"((c)[3])              \
        : "r"((a)[0]), "r"((a)[1]), "r"((a)[2]), "r"((a)[3]),                 \
          "r"((b)[0]), "r"((b)[1]))

// ---------------------------------------------------------------------------
// Kernel 1: bf16-convert all inputs into scratch + exact fp32 squared norms.
// ---------------------------------------------------------------------------
__global__ void prep_kernel(const float* __restrict__ X, const float* __restrict__ P,
                            const float* __restrict__ Q, const float* __restrict__ M) {
    int gwarp = (blockIdx.x * blockDim.x + threadIdx.x) >> 5;
    int lane  = threadIdx.x & 31;
    const float* src; float* nrm; __nv_bfloat16* dstB;
    if (gwarp < N_IMG) {
        src = X + (size_t)gwarp * DIM;  nrm = g_x2 + gwarp;  dstB = g_Ab + (size_t)gwarp * DIM;
    } else {
        int yr = gwarp - N_IMG;
        if (yr < 4096)       src = P + (size_t)yr * DIM;
        else if (yr < 8192)  src = Q + (size_t)(yr - 4096) * DIM;
        else                 src = M + (size_t)(yr - 8192) * DIM;
        nrm = g_y2 + yr;  dstB = g_Yb + (size_t)yr * DIM;
    }

    float4 v = ((const float4*)src)[lane];
    float s = v.x * v.x + v.y * v.y + v.z * v.z + v.w * v.w;
    __nv_bfloat162 lo = __floats2bfloat162_rn(v.x, v.y);
    __nv_bfloat162 hi = __floats2bfloat162_rn(v.z, v.w);
    uint2 packed = make_uint2(*(uint32_t*)&lo, *(uint32_t*)&hi);
    ((uint2*)dstB)[lane] = packed;

    #pragma unroll
    for (int o = 16; o > 0; o >>= 1) s += __shfl_xor_sync(0xFFFFFFFFu, s, o);
    if (lane == 0) {
        *nrm = s;
        if (gwarp < N_IMG) { g_Spos[gwarp] = 0.0f; g_Sden[gwarp] = 0.0f; }
    }
}

// ---------------------------------------------------------------------------
// Tile loaders into padded smem (row = 272B). 256-thread and 128-thread forms.
// ---------------------------------------------------------------------------
__device__ __forceinline__ void load_tile_cta(uint32_t sb, uint32_t byteOff,
                                              const __nv_bfloat16* src, int tid) {
    #pragma unroll
    for (int it = 0; it < 8; ++it) {
        int idx = it * 256 + tid;
        int row = idx >> 4;
        int ch  = idx & 15;
        CP16(sb + byteOff + (uint32_t)(row * 272 + ch * 16),
             src + (size_t)row * DIM + ch * 8);
    }
}
__device__ __forceinline__ void load_tile_wg(uint32_t sb, uint32_t byteOff,
                                             const __nv_bfloat16* src, int tidg) {
    #pragma unroll
    for (int it = 0; it < 16; ++it) {
        int idx = it * 128 + tidg;
        int row = idx >> 4;
        int ch  = idx & 15;
        CP16(sb + byteOff + (uint32_t)(row * 272 + ch * 16),
             src + (size_t)row * DIM + ch * 8);
    }
}

// ---------------------------------------------------------------------------
// Kernel 2: persistent-A bf16 mma.sync GEMM with warp-group phase overlap.
// 128 CTAs (4 col groups x 32 row tiles), 8 warps. Warps 0-3 (group 0) handle
// even tiles; warps 4-7 (group 1) odd tiles. One warp of each group lives on
// each SMSP, so one group's tensor-pipe GEMM overlaps the other group's
// MUFU-bound epilogue via the warp scheduler. Warp tile 64x64.
// ---------------------------------------------------------------------------
__global__ __launch_bounds__(256, 1)
void softnn_mma_kernel() {
    extern __shared__ float smem[];
    const uint32_t sb = smem_u32(smem);
    const uint32_t* smw = (const uint32_t*)smem;

    const int tid  = threadIdx.x;
    const int wid  = tid >> 5;
    const int lane = tid & 31;
    const int gid  = lane >> 2;          // 0..7
    const int tig  = lane & 3;           // 0..3
    const int grp  = wid >> 2;           // warp group 0/1
    const int wg   = wid & 3;            // warp within group
    const int tidg = tid & 127;          // thread within group
    const int mbase = (wg >> 1) * 64;    // 64-row half
    const int nbase = (wg & 1) * 64;     // 64-col half

    const int c       = blockIdx.x;               // column group 0..3
    const int rowBase = blockIdx.y * TILE;
    const __nv_bfloat16* Ybase = g_Yb + (size_t)(c * TILES_PER_CTA) * TILE * DIM;

    // Buffer byte offsets: A at 0; group g uses B buffers (1+2g), (2+2g).
    const uint32_t bufOff[2] = { (uint32_t)((1 + 2 * grp) * TILE_SMB),
                                 (uint32_t)((2 + 2 * grp) * TILE_SMB) };

    // commit 1: A (all 256 threads)
    load_tile_cta(sb, 0, g_Ab + (size_t)rowBase * DIM, tid);
    CP_COMMIT();
    // commits 2,3: this group's first two tiles (flat indices grp, grp+2)
    load_tile_wg(sb, bufOff[0], Ybase + (size_t)grp * TILE * DIM, tidg);
    CP_COMMIT();
    load_tile_wg(sb, bufOff[1], Ybase + (size_t)(grp + 2) * TILE * DIM, tidg);
    CP_COMMIT();

    CP_WAIT(2);          // A complete (2 B loads may remain in flight)
    __syncthreads();     // A visible to all; groups decouple after this

    // Persistent per-thread row norms (rows: mbase + i*16 + gid (+8))
    float x2v[8];
    #pragma unroll
    for (int i = 0; i < 4; ++i) {
        x2v[2*i]   = g_x2[rowBase + mbase + i * 16 + gid];
        x2v[2*i+1] = g_x2[rowBase + mbase + i * 16 + gid + 8];
    }

    float sumP[8], sumD[8], acc[4][8][4];
    #pragma unroll
    for (int r = 0; r < 8; ++r) { sumP[r] = 0.0f; sumD[r] = 0.0f; }
    #pragma unroll
    for (int i = 0; i < 4; ++i)
        #pragma unroll
        for (int j = 0; j < 8; ++j)
            #pragma unroll
            for (int q = 0; q < 4; ++q) acc[i][j][q] = 0.0f;

    const uint32_t* A = smw;

    for (int k = 0; k < TILES_PER_WG; ++k) {
        const int tau = 2 * k + grp;              // this group's flat tile
        const int gt  = c * TILES_PER_CTA + tau;  // global col tile 0..191

        CP_WAIT(1);                               // buf[k&1] holds tile tau
        BARG(grp);                                // whole group sees it

        // ---- GEMM 128(rows)x64(cols per warp)x128 ----
        const uint32_t* B = smw + (bufOff[k & 1] >> 2);
        #pragma unroll
        for (int ks = 0; ks < 8; ++ks) {
            const int kw = ks * 8;
            uint32_t Af[4][4], Bf[8][2];
            #pragma unroll
            for (int i = 0; i < 4; ++i) {
                const uint32_t* p = A + (mbase + i * 16 + gid) * LDWRD + kw + tig;
                Af[i][0] = p[0]; Af[i][1] = p[8 * LDWRD];
                Af[i][2] = p[4]; Af[i][3] = p[8 * LDWRD + 4];
            }
            #pragma unroll
            for (int j = 0; j < 8; ++j) {
                const uint32_t* p = B + (nbase + j * 8 + gid) * LDWRD + kw + tig;
                Bf[j][0] = p[0]; Bf[j][1] = p[4];
            }
            #pragma unroll
            for (int i = 0; i < 4; ++i)
                #pragma unroll
                for (int j = 0; j < 8; ++j)
                    MMA_BF16(acc[i][j], Af[i], Bf[j]);
        }

        BARG(grp);                                // group done reading buf[k&1]
        if (k + 2 < TILES_PER_WG)
            load_tile_wg(sb, bufOff[k & 1],
                         Ybase + (size_t)(2 * (k + 2) + grp) * TILE * DIM, tidg);
        CP_COMMIT();                              // keep group accounting

        // ---- Epilogue (register-local; overlaps other group's GEMM) ----
        const float nc = (gt < Q_TILE_END) ? -5.7707801635558537f   // -4*log2(e)
                                           : -2.8853900817779268f;  // -2*log2(e)
        float tsum[8];
        #pragma unroll
        for (int r = 0; r < 8; ++r) tsum[r] = 0.0f;

        #pragma unroll
        for (int j = 0; j < 8; ++j) {
            const int n0 = gt * TILE + nbase + j * 8 + 2 * tig;
            const float y0 = __ldg(&g_y2[n0]);
            const float y1 = __ldg(&g_y2[n0 + 1]);
            #pragma unroll
            for (int i = 0; i < 4; ++i) {
                float s00 = fmaxf(fmaf(-2.0f, acc[i][j][0], x2v[2*i]   + y0), 0.0f);
                float s01 = fmaxf(fmaf(-2.0f, acc[i][j][1], x2v[2*i]   + y1), 0.0f);
                float s10 = fmaxf(fmaf(-2.0f, acc[i][j][2], x2v[2*i+1] + y0), 0.0f);
                float s11 = fmaxf(fmaf(-2.0f, acc[i][j][3], x2v[2*i+1] + y1), 0.0f);
                tsum[2*i]   += ex2_approx(nc * sqrt_approx(s00)) + ex2_approx(nc * sqrt_approx(s01));
                tsum[2*i+1] += ex2_approx(nc * sqrt_approx(s10)) + ex2_approx(nc * sqrt_approx(s11));
                acc[i][j][0] = 0.0f; acc[i][j][1] = 0.0f;
                acc[i][j][2] = 0.0f; acc[i][j][3] = 0.0f;
            }
        }
        if (gt < P_TILE_END) {
            #pragma unroll
            for (int r = 0; r < 8; ++r) sumP[r] += tsum[r];
        } else {
            #pragma unroll
            for (int r = 0; r < 8; ++r) sumD[r] += tsum[r];
        }
    }

    // Reduce the 4 tig lanes (which share rows, cover 64 cols) and flush.
    #pragma unroll
    for (int r = 0; r < 8; ++r) {
        float p = sumP[r], d = sumD[r];
        p += __shfl_xor_sync(0xFFFFFFFFu, p, 1);
        p += __shfl_xor_sync(0xFFFFFFFFu, p, 2);
        d += __shfl_xor_sync(0xFFFFFFFFu, d, 1);
        d += __shfl_xor_sync(0xFFFFFFFFu, d, 2);
        if (tig == 0) {
            int row = rowBase + mbase + (r >> 1) * 16 + gid + (r & 1) * 8;
            atomicAdd(&g_Spos[row], p);
            atomicAdd(&g_Sden[row], d);
        }
    }
}

// ---------------------------------------------------------------------------
// Kernel 3: loss = sum_i ( log(Sden[i]) - log(Spos[i]) )
// ---------------------------------------------------------------------------
__global__ void final_kernel(float* __restrict__ out) {
    __shared__ double sm[256];
    int tid = threadIdx.x;
    double acc = 0.0;
    for (int i = tid; i < N_IMG; i += 256)
        acc += (double)(logf(g_Sden[i]) - logf(g_Spos[i]));
    sm[tid] = acc;
    __syncthreads();
    for (int o = 128; o > 0; o >>= 1) {
        if (tid < o) sm[tid] += sm[tid + o];
        __syncthreads();
    }
    if (tid == 0) out[0] = (float)sm[0];
}

// ---------------------------------------------------------------------------
extern "C" void kernel_launch(void* const* d_in, const int* in_sizes, int n_in,
                              void* d_out, int out_size) {
    const float* X = (const float*)d_in[0];   // image_views      [4096,128]
    const float* P = (const float*)d_in[1];   // positive_views   [4096,128]
    const float* Q = (const float*)d_in[2];   // negative_views   [4096,128]
    const float* M = (const float*)d_in[3];   // other_embeddings [16384,128]

    cudaFuncSetAttribute(softnn_mma_kernel,
                         cudaFuncAttributeMaxDynamicSharedMemorySize, SMEM_BYTES);

    prep_kernel<<<(N_IMG + N_YTOT) / 8, 256>>>(X, P, Q, M);

    dim3 grid(N_GROUPS, N_IMG / TILE);       // 4 x 32 = 128 CTAs
    softnn_mma_kernel<<<grid, 256, SMEM_BYTES>>>();

    final_kernel<<<1, 256>>>((float*)d_out);
}